// round 13
// baseline (speedup 1.0000x reference)
#include <cuda_runtime.h>
#include <cuda_fp16.h>
#include <math.h>
#include <stdint.h>

// ---------------- problem constants ----------------------------------------
#define S_TOK 1536
#define S0    1024
#define HID   1024
#define HEADS 16
#define HD    64
#define INTER 4096
#define NLAYERS 4
#define KPATCH 768

// ---------------- scratch ---------------------------------------------------
__device__ float g_x [S_TOK * HID];
__device__ float g_h2[S_TOK * HID];
__device__ float g_cos[S_TOK * HD];
__device__ float g_sin[S_TOK * HD];
__device__ __half a_xpatch[S_TOK * KPATCH];
__device__ __half a_hn[S_TOK * HID];
__device__ __half a_q [S_TOK * HID];
__device__ __half a_k [S_TOK * HID];
__device__ __half a_v [S_TOK * HID];
__device__ __half a_ao[S_TOK * HID];
__device__ __half a_t [S_TOK * INTER];
__device__ __half h_wconv[HID * KPATCH];
__device__ __half h_wq[NLAYERS * HID * HID];
__device__ __half h_wk[NLAYERS * HID * HID];
__device__ __half h_wv[NLAYERS * HID * HID];
__device__ __half h_wo[NLAYERS * HID * HID];
__device__ __half h_wg[NLAYERS * INTER * HID];
__device__ __half h_wu[NLAYERS * INTER * HID];
__device__ __half h_wd[NLAYERS * HID * INTER];

// ---------------- helpers ----------------------------------------------------
__device__ __forceinline__ uint32_t smem_u32(const void* p) {
    return (uint32_t)__cvta_generic_to_shared(p);
}
__device__ __forceinline__ void mma_f16(float c[4], const uint32_t a[4],
                                        uint32_t b0, uint32_t b1) {
    asm volatile(
        "mma.sync.aligned.m16n8k16.row.col.f32.f16.f16.f32 "
        "{%0,%1,%2,%3},{%4,%5,%6,%7},{%8,%9},{%0,%1,%2,%3};"
        : "+f"(c[0]), "+f"(c[1]), "+f"(c[2]), "+f"(c[3])
        : "r"(a[0]), "r"(a[1]), "r"(a[2]), "r"(a[3]), "r"(b0), "r"(b1));
}
__device__ __forceinline__ void ldm_x4(uint32_t& r0, uint32_t& r1, uint32_t& r2, uint32_t& r3,
                                       uint32_t addr) {
    asm volatile("ldmatrix.sync.aligned.m8n8.x4.shared.b16 {%0,%1,%2,%3}, [%4];"
                 : "=r"(r0), "=r"(r1), "=r"(r2), "=r"(r3) : "r"(addr));
}
__device__ __forceinline__ void ldm_x4t(uint32_t& r0, uint32_t& r1, uint32_t& r2, uint32_t& r3,
                                        uint32_t addr) {
    asm volatile("ldmatrix.sync.aligned.m8n8.x4.trans.shared.b16 {%0,%1,%2,%3}, [%4];"
                 : "=r"(r0), "=r"(r1), "=r"(r2), "=r"(r3) : "r"(addr));
}
__device__ __forceinline__ void cp16(void* smem_dst, const void* gsrc) {
    uint32_t d = (uint32_t)__cvta_generic_to_shared(smem_dst);
    asm volatile("cp.async.cg.shared.global [%0], [%1], 16;\n" :: "r"(d), "l"(gsrc));
}
#define CP_COMMIT() asm volatile("cp.async.commit_group;\n" ::: "memory")
#define CP_WAIT0()  asm volatile("cp.async.wait_group 0;\n" ::: "memory")
#define CP_WAIT1()  asm volatile("cp.async.wait_group 1;\n" ::: "memory")

// ---------------- f2h helpers -------------------------------------------------
__device__ __forceinline__ void f2h16(const float* src, __half* dst, int u) {
    const float4* x4 = (const float4*)src;
    float4 v0 = x4[4 * u + 0];
    float4 v1 = x4[4 * u + 1];
    float4 v2 = x4[4 * u + 2];
    float4 v3 = x4[4 * u + 3];
    __half2 h0 = __floats2half2_rn(v0.x, v0.y), h1 = __floats2half2_rn(v0.z, v0.w);
    __half2 h2 = __floats2half2_rn(v1.x, v1.y), h3 = __floats2half2_rn(v1.z, v1.w);
    __half2 h4 = __floats2half2_rn(v2.x, v2.y), h5 = __floats2half2_rn(v2.z, v2.w);
    __half2 h6 = __floats2half2_rn(v3.x, v3.y), h7 = __floats2half2_rn(v3.z, v3.w);
    uint4 ua, ub;
    ua.x = *(uint32_t*)&h0; ua.y = *(uint32_t*)&h1;
    ua.z = *(uint32_t*)&h2; ua.w = *(uint32_t*)&h3;
    ub.x = *(uint32_t*)&h4; ub.y = *(uint32_t*)&h5;
    ub.z = *(uint32_t*)&h6; ub.w = *(uint32_t*)&h7;
    ((uint4*)dst)[2 * u + 0] = ua;
    ((uint4*)dst)[2 * u + 1] = ub;
}

// conv weight (single array)
__global__ void f2h_kernel(const float* __restrict__ x, __half* __restrict__ y, int n16) {
    int i = blockIdx.x * blockDim.x + threadIdx.x;
    if (i >= n16) return;
    f2h16(x, y, i);
}

// all 7 weight arrays of one layer in a single launch
// units of 16 floats: q/k/v/o = 65536 units each, g/u/d = 262144 units each
__global__ void __launch_bounds__(256) f2h_batch(
    const float* __restrict__ qw, const float* __restrict__ kw,
    const float* __restrict__ vw, const float* __restrict__ ow,
    const float* __restrict__ gw, const float* __restrict__ uw,
    const float* __restrict__ dw,
    __half* oq, __half* ok, __half* ov, __half* oo,
    __half* og, __half* ou, __half* od)
{
    int u = blockIdx.x * 256 + threadIdx.x;   // < 1048576
    if (u < 262144) {
        int a = u >> 16, off = u & 65535;
        const float* s = (a == 0) ? qw : (a == 1) ? kw : (a == 2) ? vw : ow;
        __half*      d = (a == 0) ? oq : (a == 1) ? ok : (a == 2) ? ov : oo;
        f2h16(s, d, off);
    } else {
        int u2 = u - 262144;
        int a = u2 >> 18, off = u2 & 262143;
        const float* s = (a == 0) ? gw : (a == 1) ? uw : dw;
        __half*      d = (a == 0) ? og : (a == 1) ? ou : od;
        f2h16(s, d, off);
    }
}

// ---------------- prep: im2col + rope table in one launch ----------------------
#define IM2COL_BLOCKS 4608   // 1536*768/256
__global__ void __launch_bounds__(256) prep_kernel(
    const float* __restrict__ img0, const float* __restrict__ img1)
{
    if (blockIdx.x < IM2COL_BLOCKS) {
        int idx = blockIdx.x * 256 + threadIdx.x;
        int s = idx / KPATCH;
        int r = idx - s * KPATCH;
        int c  = r >> 8;
        int kh = (r >> 4) & 15;
        int kw = r & 15;
        float val;
        if (s < S0) {
            int ph = s >> 5, pw = s & 31;
            val = img0[c * 512 * 512 + (ph * 16 + kh) * 512 + (pw * 16 + kw)];
        } else {
            int sp = s - S0;
            int ph = sp >> 4, pw = sp & 15;
            val = img1[c * 512 * 256 + (ph * 16 + kh) * 256 + (pw * 16 + kw)];
        }
        a_xpatch[idx] = __float2half(val);
    } else {
        int b = blockIdx.x - IM2COL_BLOCKS;
        int s = b * 4 + (threadIdx.x >> 6);
        int d = threadIdx.x & 63;
        int ph, pw;
        if (s < S0) { ph = s >> 5; pw = s & 31; }
        else        { int sp = s - S0; ph = sp >> 4; pw = sp & 15; }
        int j = d & 31;
        float e, base;
        if (j < 16) { e = (4.0f * j) / 64.0f;               base = (float)ph; }
        else        { e = (2.0f + 4.0f * (j - 16)) / 64.0f; base = (float)pw; }
        float f = base * expf(-e * 9.2103403719761836f);
        g_cos[s * HD + d] = cosf(f);
        g_sin[s * HD + d] = sinf(f);
    }
}

// ---------------- RMSNorm -------------------------------------------------------
template<bool OUT_HALF>
__global__ void rms_kernel(const float* __restrict__ x,
                           const float* __restrict__ w,
                           void* __restrict__ yv) {
    int s = blockIdx.x;
    int tid = threadIdx.x;  // 256
    const float* xr = x + s * HID;
    float ss = 0.f;
    #pragma unroll 4
    for (int i = tid; i < HID; i += 256) { float v = xr[i]; ss += v * v; }
    __shared__ float sh[8];
    #pragma unroll
    for (int o = 16; o > 0; o >>= 1) ss += __shfl_xor_sync(0xffffffffu, ss, o);
    if ((tid & 31) == 0) sh[tid >> 5] = ss;
    __syncthreads();
    if (tid < 8) {
        float v = sh[tid];
        #pragma unroll
        for (int o = 4; o > 0; o >>= 1) v += __shfl_xor_sync(0xffu, v, o);
        if (tid == 0) sh[0] = v;
    }
    __syncthreads();
    float r = rsqrtf(sh[0] * (1.0f / HID) + 1e-5f);
    if (OUT_HALF) {
        __half* y = (__half*)yv;
        for (int i = tid; i < HID; i += 256) y[s * HID + i] = __float2half(xr[i] * r * w[i]);
    } else {
        float* y = (float*)yv;
        for (int i = tid; i < HID; i += 256) y[s * HID + i] = xr[i] * r * w[i];
    }
}

#define SROWH 72   // halves per smem row (64 data + 8 pad)
#define SROW2 40   // halves per row for BK=32 (32 data + 8 pad)

// ---------------- fp16 GEMM core (64x128x64, 2m x 4n warps) --------------------
// Returns with accumulators in acc[][]; caller does epilogue.
template<int EPI, bool OUT_HALF>
__device__ __forceinline__ void gemm_body(
    const __half* __restrict__ A, const __half* __restrict__ B,
    const void* __restrict__ auxp, void* __restrict__ Cp,
    int N, int K, __half* tiles)
{
    constexpr int BM = 64;
    constexpr int MT = 2;
    constexpr int ASTG = BM * SROWH;
    constexpr int BSTG = 128 * SROWH;
    constexpr int STG  = ASTG + BSTG;

    int tid = threadIdx.x;
    int warp = tid >> 5, lane = tid & 31;
    int gid = lane >> 2, tig = lane & 3;
    int g8 = lane >> 3, r8 = lane & 7;
    int wm = warp >> 2, wn = warp & 3;
    int m0 = blockIdx.y * BM, n0 = blockIdx.x * 128;

    float acc[MT][4][4];
    #pragma unroll
    for (int i = 0; i < MT; i++)
        #pragma unroll
        for (int j = 0; j < 4; j++)
            #pragma unroll
            for (int l = 0; l < 4; l++) acc[i][j][l] = 0.f;

    const int KT = K >> 6;
    constexpr int NCH = (BM + 128) * 8;

    auto load_stage = [&](int kt, int s) {
        int k0 = kt << 6;
        __half* As = tiles + s * STG;
        __half* Bs = As + ASTG;
        #pragma unroll
        for (int i = tid; i < NCH; i += 256) {
            int r = i >> 3, c = (i & 7) << 3;
            if (r < BM) cp16(&As[r * SROWH + c], &A[(size_t)(m0 + r) * K + k0 + c]);
            else {
                int rb = r - BM;
                cp16(&Bs[rb * SROWH + c], &B[(size_t)(n0 + rb) * K + k0 + c]);
            }
        }
        CP_COMMIT();
    };

    uint32_t a_off[MT], b_off[2];
    #pragma unroll
    for (int i = 0; i < MT; i++)
        a_off[i] = (uint32_t)(((wm * 32 + i * 16 + (g8 & 1) * 8 + r8) * SROWH) * 2
                              + (g8 >> 1) * 16);
    #pragma unroll
    for (int jj = 0; jj < 2; jj++)
        b_off[jj] = (uint32_t)(ASTG * 2 + ((wn * 32 + jj * 16 + (g8 >> 1) * 8 + r8) * SROWH) * 2
                               + (g8 & 1) * 16);

    load_stage(0, 0);
    load_stage(1, 1);

    for (int kt = 0; kt < KT; kt++) {
        int s = kt % 3;
        if (kt + 1 < KT) CP_WAIT1(); else CP_WAIT0();
        __syncthreads();
        if (kt + 2 < KT) load_stage(kt + 2, (kt + 2) % 3);
        uint32_t base = smem_u32(tiles + s * STG);
        #pragma unroll
        for (int ks = 0; ks < 4; ks++) {
            uint32_t kofs = base + ks * 32;
            uint32_t af[MT][4];
            #pragma unroll
            for (int i = 0; i < MT; i++)
                ldm_x4(af[i][0], af[i][1], af[i][2], af[i][3], kofs + a_off[i]);
            uint32_t bf[4][2];
            #pragma unroll
            for (int jj = 0; jj < 2; jj++) {
                uint32_t m0r, m1r, m2r, m3r;
                ldm_x4(m0r, m1r, m2r, m3r, kofs + b_off[jj]);
                bf[2 * jj + 0][0] = m0r; bf[2 * jj + 0][1] = m1r;
                bf[2 * jj + 1][0] = m2r; bf[2 * jj + 1][1] = m3r;
            }
            #pragma unroll
            for (int i = 0; i < MT; i++)
                #pragma unroll
                for (int j = 0; j < 4; j++)
                    mma_f16(acc[i][j], af[i], bf[j][0], bf[j][1]);
        }
    }

    const float* auxf = (const float*)auxp;
    #pragma unroll
    for (int i = 0; i < MT; i++) {
        #pragma unroll
        for (int j = 0; j < 4; j++) {
            int m = m0 + wm * 32 + i * 16 + gid;
            int n = n0 + wn * 32 + j * 8 + 2 * tig;
            #pragma unroll
            for (int hh = 0; hh < 2; hh++) {
                int mm = m + hh * 8;
                float v0 = acc[i][j][hh * 2 + 0];
                float v1 = acc[i][j][hh * 2 + 1];
                size_t off = (size_t)mm * N + n;
                if (EPI == 1) { v0 += auxf[off]; v1 += auxf[off + 1]; }
                if (OUT_HALF) {
                    *(__half2*)&((__half*)Cp)[off] = __floats2half2_rn(v0, v1);
                } else {
                    float2 o2; o2.x = v0; o2.y = v1;
                    *(float2*)&((float*)Cp)[off] = o2;
                }
            }
        }
    }
}

template<int EPI, bool OUT_HALF>
__global__ void __launch_bounds__(256) gemm_f16(
    const __half* __restrict__ A, const __half* __restrict__ B,
    const void* __restrict__ aux, void* __restrict__ C, int N, int K)
{
    extern __shared__ __half tiles[];
    gemm_body<EPI, OUT_HALF>(A, B, aux, C, N, K, tiles);
}

// ---------------- QKV GEMM with fused RoPE epilogue -----------------------------
// z=0 -> Q (rope + 0.125 scale), z=1 -> K (rope), z=2 -> V (plain).
#define CSR 136   // staging row stride (halves): 128 data + 8 pad

__global__ void __launch_bounds__(256) gemm_qkv(
    const __half* __restrict__ A,
    const __half* __restrict__ B0, const __half* __restrict__ B1, const __half* __restrict__ B2,
    __half* __restrict__ C0, __half* __restrict__ C1, __half* __restrict__ C2, int K)
{
    extern __shared__ __half tiles[];
    constexpr int BM = 64;
    constexpr int MT = 2;
    constexpr int ASTG = BM * SROWH;
    constexpr int BSTG = 128 * SROWH;
    constexpr int STG  = ASTG + BSTG;

    int zsel = blockIdx.z;
    const __half* B = (zsel == 0) ? B0 : (zsel == 1) ? B1 : B2;
    __half*       C = (zsel == 0) ? C0 : (zsel == 1) ? C1 : C2;

    int tid = threadIdx.x;
    int warp = tid >> 5, lane = tid & 31;
    int gid = lane >> 2, tig = lane & 3;
    int g8 = lane >> 3, r8 = lane & 7;
    int wm = warp >> 2, wn = warp & 3;
    int m0 = blockIdx.y * BM, n0 = blockIdx.x * 128;

    float acc[MT][4][4];
    #pragma unroll
    for (int i = 0; i < MT; i++)
        #pragma unroll
        for (int j = 0; j < 4; j++)
            #pragma unroll
            for (int l = 0; l < 4; l++) acc[i][j][l] = 0.f;

    const int KT = K >> 6;
    constexpr int NCH = (BM + 128) * 8;

    auto load_stage = [&](int kt, int s) {
        int k0 = kt << 6;
        __half* As = tiles + s * STG;
        __half* Bs = As + ASTG;
        #pragma unroll
        for (int i = tid; i < NCH; i += 256) {
            int r = i >> 3, c = (i & 7) << 3;
            if (r < BM) cp16(&As[r * SROWH + c], &A[(size_t)(m0 + r) * K + k0 + c]);
            else {
                int rb = r - BM;
                cp16(&Bs[rb * SROWH + c], &B[(size_t)(n0 + rb) * K + k0 + c]);
            }
        }
        CP_COMMIT();
    };

    uint32_t a_off[MT], b_off[2];
    #pragma unroll
    for (int i = 0; i < MT; i++)
        a_off[i] = (uint32_t)(((wm * 32 + i * 16 + (g8 & 1) * 8 + r8) * SROWH) * 2
                              + (g8 >> 1) * 16);
    #pragma unroll
    for (int jj = 0; jj < 2; jj++)
        b_off[jj] = (uint32_t)(ASTG * 2 + ((wn * 32 + jj * 16 + (g8 >> 1) * 8 + r8) * SROWH) * 2
                               + (g8 & 1) * 16);

    load_stage(0, 0);
    load_stage(1, 1);

    for (int kt = 0; kt < KT; kt++) {
        int s = kt % 3;
        if (kt + 1 < KT) CP_WAIT1(); else CP_WAIT0();
        __syncthreads();
        if (kt + 2 < KT) load_stage(kt + 2, (kt + 2) % 3);
        uint32_t base = smem_u32(tiles + s * STG);
        #pragma unroll
        for (int ks = 0; ks < 4; ks++) {
            uint32_t kofs = base + ks * 32;
            uint32_t af[MT][4];
            #pragma unroll
            for (int i = 0; i < MT; i++)
                ldm_x4(af[i][0], af[i][1], af[i][2], af[i][3], kofs + a_off[i]);
            uint32_t bf[4][2];
            #pragma unroll
            for (int jj = 0; jj < 2; jj++) {
                uint32_t m0r, m1r, m2r, m3r;
                ldm_x4(m0r, m1r, m2r, m3r, kofs + b_off[jj]);
                bf[2 * jj + 0][0] = m0r; bf[2 * jj + 0][1] = m1r;
                bf[2 * jj + 1][0] = m2r; bf[2 * jj + 1][1] = m3r;
            }
            #pragma unroll
            for (int i = 0; i < MT; i++)
                #pragma unroll
                for (int j = 0; j < 4; j++)
                    mma_f16(acc[i][j], af[i], bf[j][0], bf[j][1]);
        }
    }

    if (zsel < 2) {
        // stage C tile in smem, then rope across the (d, d+32) pairing
        __syncthreads();   // all smem reads from mainloop complete
        __half* Cs = tiles;   // 64 x CSR halves = 17408 B
        #pragma unroll
        for (int i = 0; i < MT; i++)
            #pragma unroll
            for (int j = 0; j < 4; j++) {
                int rr = wm * 32 + i * 16 + gid;
                int cc = wn * 32 + j * 8 + 2 * tig;
                #pragma unroll
                for (int hh = 0; hh < 2; hh++)
                    *(__half2*)&Cs[(rr + hh * 8) * CSR + cc] =
                        __floats2half2_rn(acc[i][j][hh * 2], acc[i][j][hh * 2 + 1]);
            }
        __syncthreads();

        float qscale = (zsel == 0) ? 0.125f : 1.0f;
        // 64 rows x 2 heads x 32 pair-dims = 4096 pairs, 16 per thread
        for (int e = tid; e < 4096; e += 256) {
            int d  = e & 31;
            int hh = (e >> 5) & 1;
            int r  = e >> 6;
            int token = m0 + r;
            float c  = g_cos[token * HD + d];
            float sn = g_sin[token * HD + d];
            float v0 = __half2float(Cs[r * CSR + hh * 64 + d]);
            float v1 = __half2float(Cs[r * CSR + hh * 64 + d + 32]);
            float o0 = (v0 * c - v1 * sn) * qscale;
            float o1 = (v1 * c + v0 * sn) * qscale;
            size_t gb = (size_t)token * HID + n0 + hh * 64 + d;
            C[gb]      = __float2half(o0);
            C[gb + 32] = __float2half(o1);
        }
    } else {
        // plain V epilogue
        #pragma unroll
        for (int i = 0; i < MT; i++)
            #pragma unroll
            for (int j = 0; j < 4; j++) {
                int m = m0 + wm * 32 + i * 16 + gid;
                int n = n0 + wn * 32 + j * 8 + 2 * tig;
                #pragma unroll
                for (int hh = 0; hh < 2; hh++) {
                    size_t off = (size_t)(m + hh * 8) * HID + n;
                    *(__half2*)&C[off] =
                        __floats2half2_rn(acc[i][j][hh * 2], acc[i][j][hh * 2 + 1]);
                }
            }
    }
}

// ---------------- fused gate||up GEMM (64x128x32) with SiLU ---------------------
__global__ void __launch_bounds__(256) gemm_gateup(
    const __half* __restrict__ A, const __half* __restrict__ G,
    const __half* __restrict__ U, __half* __restrict__ C, int N, int K)
{
    extern __shared__ __half tiles[];
    constexpr int BM = 64;
    constexpr int ASTG = BM * SROW2;
    constexpr int BSTG = 128 * SROW2;
    constexpr int STG  = ASTG + 2 * BSTG;

    int tid = threadIdx.x;
    int warp = tid >> 5, lane = tid & 31;
    int gid = lane >> 2, tig = lane & 3;
    int g8 = lane >> 3, r8 = lane & 7;
    int wm = warp >> 2, wn = warp & 3;
    int m0 = blockIdx.y * BM, n0 = blockIdx.x * 128;

    float accg[2][4][4], accu[2][4][4];
    #pragma unroll
    for (int i = 0; i < 2; i++)
        #pragma unroll
        for (int j = 0; j < 4; j++)
            #pragma unroll
            for (int l = 0; l < 4; l++) { accg[i][j][l] = 0.f; accu[i][j][l] = 0.f; }

    const int KT = K >> 5;
    constexpr int NCH = (BM + 256) * 4;

    auto load_stage = [&](int kt, int s) {
        int k0 = kt << 5;
        __half* As = tiles + s * STG;
        __half* Gs = As + ASTG;
        __half* Us = Gs + BSTG;
        #pragma unroll
        for (int i = tid; i < NCH; i += 256) {
            int r = i >> 2, c = (i & 3) << 3;
            if (r < BM) cp16(&As[r * SROW2 + c], &A[(size_t)(m0 + r) * K + k0 + c]);
            else if (r < BM + 128) {
                int rb = r - BM;
                cp16(&Gs[rb * SROW2 + c], &G[(size_t)(n0 + rb) * K + k0 + c]);
            } else {
                int rb = r - BM - 128;
                cp16(&Us[rb * SROW2 + c], &U[(size_t)(n0 + rb) * K + k0 + c]);
            }
        }
        CP_COMMIT();
    };

    uint32_t a_off[2], g_off[2], u_off[2];
    #pragma unroll
    for (int i = 0; i < 2; i++)
        a_off[i] = (uint32_t)(((wm * 32 + i * 16 + (g8 & 1) * 8 + r8) * SROW2) * 2
                              + (g8 >> 1) * 16);
    #pragma unroll
    for (int jj = 0; jj < 2; jj++) {
        uint32_t row = (uint32_t)(wn * 32 + jj * 16 + (g8 >> 1) * 8 + r8);
        g_off[jj] = (uint32_t)(ASTG * 2 + (row * SROW2) * 2 + (g8 & 1) * 16);
        u_off[jj] = g_off[jj] + BSTG * 2;
    }

    load_stage(0, 0);
    load_stage(1, 1);

    for (int kt = 0; kt < KT; kt++) {
        int s = kt % 3;
        if (kt + 1 < KT) CP_WAIT1(); else CP_WAIT0();
        __syncthreads();
        if (kt + 2 < KT) load_stage(kt + 2, (kt + 2) % 3);
        uint32_t base = smem_u32(tiles + s * STG);
        #pragma unroll
        for (int ks = 0; ks < 2; ks++) {
            uint32_t kofs = base + ks * 32;
            uint32_t af[2][4];
            #pragma unroll
            for (int i = 0; i < 2; i++)
                ldm_x4(af[i][0], af[i][1], af[i][2], af[i][3], kofs + a_off[i]);
            uint32_t gf[4][2], uf[4][2];
            #pragma unroll
            for (int jj = 0; jj < 2; jj++) {
                uint32_t m0r, m1r, m2r, m3r;
                ldm_x4(m0r, m1r, m2r, m3r, kofs + g_off[jj]);
                gf[2 * jj + 0][0] = m0r; gf[2 * jj + 0][1] = m1r;
                gf[2 * jj + 1][0] = m2r; gf[2 * jj + 1][1] = m3r;
                ldm_x4(m0r, m1r, m2r, m3r, kofs + u_off[jj]);
                uf[2 * jj + 0][0] = m0r; uf[2 * jj + 0][1] = m1r;
                uf[2 * jj + 1][0] = m2r; uf[2 * jj + 1][1] = m3r;
            }
            #pragma unroll
            for (int i = 0; i < 2; i++)
                #pragma unroll
                for (int j = 0; j < 4; j++) {
                    mma_f16(accg[i][j], af[i], gf[j][0], gf[j][1]);
                    mma_f16(accu[i][j], af[i], uf[j][0], uf[j][1]);
                }
        }
    }

    #pragma unroll
    for (int i = 0; i < 2; i++) {
        #pragma unroll
        for (int j = 0; j < 4; j++) {
            int m = m0 + wm * 32 + i * 16 + gid;
            int n = n0 + wn * 32 + j * 8 + 2 * tig;
            #pragma unroll
            for (int hh = 0; hh < 2; hh++) {
                int mm = m + hh * 8;
                float gg0 = accg[i][j][hh * 2 + 0], gg1 = accg[i][j][hh * 2 + 1];
                float v0 = accu[i][j][hh * 2 + 0] * gg0 / (1.0f + __expf(-gg0));
                float v1 = accu[i][j][hh * 2 + 1] * gg1 / (1.0f + __expf(-gg1));
                size_t off = (size_t)mm * N + n;
                *(__half2*)&C[off] = __floats2half2_rn(v0, v1);
            }
        }
    }
}

// ---------------- fp16 flash attention (double-buffered K/V) ---------------------
#define SP 68   // score row stride (floats)

__global__ void __launch_bounds__(256) attn_mma_kernel(
    const __half* __restrict__ q, const __half* __restrict__ k,
    const __half* __restrict__ v, __half* __restrict__ o)
{
    extern __shared__ char smraw[];
    __half* Qs = (__half*)smraw;
    __half* Kb = Qs + 64 * SROWH;
    __half* Vb = Kb + 2 * 64 * SROWH;
    __half* Ps = Vb + 2 * 64 * SROWH;
    float*  Ss = (float*)(Ps + 64 * SROWH);
    float*  Al = Ss + 64 * SP;
    float*  Ll = Al + 64;

    int qt = blockIdx.x, h = blockIdx.y;
    int s0 = qt * 64;
    int key0 = (s0 < S0) ? 0 : S0;
    int nkt  = (s0 < S0) ? 16 : 8;

    int tid = threadIdx.x;
    int warp = tid >> 5, lane = tid & 31;
    int gid = lane >> 2, tig = lane & 3;
    int g8 = lane >> 3, r8 = lane & 7;
    int wm = warp >> 1, wn = warp & 1;
    int qq = tid >> 2, kg = tid & 3;

    auto load_tile = [&](int kt) {
        __half* Kd = Kb + (kt & 1) * 64 * SROWH;
        __half* Vd = Vb + (kt & 1) * 64 * SROWH;
        for (int i = tid; i < 1024; i += 256) {
            int sel = i >> 9;
            int i2 = i & 511;
            int r = i2 >> 3, c = (i2 & 7) << 3;
            size_t g = (size_t)(key0 + kt * 64 + r) * HID + h * HD + c;
            if (sel == 0) cp16(&Kd[r * SROWH + c], &k[g]);
            else          cp16(&Vd[r * SROWH + c], &v[g]);
        }
        CP_COMMIT();
    };

    for (int i = tid; i < 512; i += 256) {
        int r = i >> 3, c = (i & 7) << 3;
        cp16(&Qs[r * SROWH + c], &q[(size_t)(s0 + r) * HID + h * HD + c]);
    }
    CP_COMMIT();
    load_tile(0);

    float m_prev = -1e30f, lsum = 0.f;
    float oacc[4][4];
    #pragma unroll
    for (int j = 0; j < 4; j++)
        #pragma unroll
        for (int l = 0; l < 4; l++) oacc[j][l] = 0.f;

    int arow0 = wm * 16 + gid;

    uint32_t qa_off = (uint32_t)(((wm * 16 + (g8 & 1) * 8 + r8) * SROWH) * 2 + (g8 >> 1) * 16);
    uint32_t kb_off[2];
    #pragma unroll
    for (int jj = 0; jj < 2; jj++)
        kb_off[jj] = (uint32_t)(((wn * 32 + jj * 16 + (g8 >> 1) * 8 + r8) * SROWH) * 2
                                + (g8 & 1) * 16);

    uint32_t qbase = smem_u32(Qs);
    uint32_t pbase = smem_u32(Ps);

    for (int kt = 0; kt < nkt; kt++) {
        CP_WAIT0();
        __syncthreads();
        if (kt + 1 < nkt) load_tile(kt + 1);

        uint32_t kbase = smem_u32(Kb + (kt & 1) * 64 * SROWH);
        uint32_t vbase = smem_u32(Vb + (kt & 1) * 64 * SROWH);

        float sc[4][4];
        #pragma unroll
        for (int j = 0; j < 4; j++)
            #pragma unroll
            for (int l = 0; l < 4; l++) sc[j][l] = 0.f;
        #pragma unroll
        for (int ks = 0; ks < 4; ks++) {
            uint32_t kofs = ks * 32;
            uint32_t aq[4];
            ldm_x4(aq[0], aq[1], aq[2], aq[3], qbase + kofs + qa_off);
            uint32_t bf[4][2];
            #pragma unroll
            for (int jj = 0; jj < 2; jj++) {
                uint32_t m0r, m1r, m2r, m3r;
                ldm_x4(m0r, m1r, m2r, m3r, kbase + kofs + kb_off[jj]);
                bf[2 * jj + 0][0] = m0r; bf[2 * jj + 0][1] = m1r;
                bf[2 * jj + 1][0] = m2r; bf[2 * jj + 1][1] = m3r;
            }
            #pragma unroll
            for (int j = 0; j < 4; j++)
                mma_f16(sc[j], aq, bf[j][0], bf[j][1]);
        }
        #pragma unroll
        for (int j = 0; j < 4; j++) {
            int cn = wn * 32 + j * 8 + 2 * tig;
            Ss[arow0 * SP + cn]           = sc[j][0];
            Ss[arow0 * SP + cn + 1]       = sc[j][1];
            Ss[(arow0 + 8) * SP + cn]     = sc[j][2];
            Ss[(arow0 + 8) * SP + cn + 1] = sc[j][3];
        }
        __syncthreads();

        {
            float e[16];
            int base = qq * SP + kg * 16;
            float mloc = -1e30f;
            #pragma unroll
            for (int i = 0; i < 16; i++) { e[i] = Ss[base + i]; mloc = fmaxf(mloc, e[i]); }
            mloc = fmaxf(mloc, __shfl_xor_sync(0xffffffffu, mloc, 1));
            mloc = fmaxf(mloc, __shfl_xor_sync(0xffffffffu, mloc, 2));
            float m_new = fmaxf(m_prev, mloc);
            float alpha = __expf(m_prev - m_new);
            float lrow = 0.f;
            int pb = qq * SROWH + kg * 16;
            #pragma unroll
            for (int i = 0; i < 16; i += 2) {
                float e0 = __expf(e[i]     - m_new);
                float e1 = __expf(e[i + 1] - m_new);
                lrow += e0 + e1;
                *(__half2*)&Ps[pb + i] = __floats2half2_rn(e0, e1);
            }
            lrow += __shfl_xor_sync(0xffffffffu, lrow, 1);
            lrow += __shfl_xor_sync(0xffffffffu, lrow, 2);
            lsum = lsum * alpha + lrow;
            m_prev = m_new;
            if (kg == 0) Al[qq] = alpha;
        }
        __syncthreads();

        float a_r0 = Al[arow0], a_r1 = Al[arow0 + 8];
        #pragma unroll
        for (int j = 0; j < 4; j++) {
            oacc[j][0] *= a_r0; oacc[j][1] *= a_r0;
            oacc[j][2] *= a_r1; oacc[j][3] *= a_r1;
        }

        #pragma unroll
        for (int ks = 0; ks < 4; ks++) {
            uint32_t ap[4];
            ldm_x4(ap[0], ap[1], ap[2], ap[3], pbase + ks * 32 + qa_off);
            uint32_t vf[4][2];
            #pragma unroll
            for (int jj = 0; jj < 2; jj++) {
                uint32_t addr = vbase
                    + (uint32_t)(((ks * 16 + (g8 & 1) * 8 + r8) * SROWH) * 2
                                 + (wn * 32 + jj * 16) * 2 + (g8 >> 1) * 16);
                uint32_t m0r, m1r, m2r, m3r;
                ldm_x4t(m0r, m1r, m2r, m3r, addr);
                vf[2 * jj + 0][0] = m0r; vf[2 * jj + 0][1] = m1r;
                vf[2 * jj + 1][0] = m2r; vf[2 * jj + 1][1] = m3r;
            }
            #pragma unroll
            for (int j = 0; j < 4; j++)
                mma_f16(oacc[j], ap, vf[j][0], vf[j][1]);
        }
        __syncthreads();
    }

    if (kg == 0) Ll[qq] = lsum;
    __syncthreads();
    float inv0 = 1.0f / Ll[arow0];
    float inv1 = 1.0f / Ll[arow0 + 8];
    #pragma unroll
    for (int j = 0; j < 4; j++) {
        int cn = wn * 32 + j * 8 + 2 * tig;
        size_t o0 = (size_t)(s0 + arow0) * HID + h * HD + cn;
        size_t o1 = (size_t)(s0 + arow0 + 8) * HID + h * HD + cn;
        *(__half2*)&o[o0] = __floats2half2_rn(oacc[j][0] * inv0, oacc[j][1] * inv0);
        *(__half2*)&o[o1] = __floats2half2_rn(oacc[j][2] * inv1, oacc[j][3] * inv1);
    }
}

// ---------------- host orchestration ---------------------------------------------
extern "C" void kernel_launch(void* const* d_in, const int* in_sizes, int n_in,
                              void* d_out, int out_size) {
    const float* img0        = (const float*)d_in[0];
    const float* img1        = (const float*)d_in[1];
    const float* conv_w      = (const float*)d_in[2];
    const float* ln_pre_w    = (const float*)d_in[3];
    const float* attn_norm_w = (const float*)d_in[4];
    const float* q_w         = (const float*)d_in[5];
    const float* k_w         = (const float*)d_in[6];
    const float* v_w         = (const float*)d_in[7];
    const float* o_w         = (const float*)d_in[8];
    const float* ffn_norm_w  = (const float*)d_in[9];
    const float* gate_w      = (const float*)d_in[10];
    const float* up_w        = (const float*)d_in[11];
    const float* down_w      = (const float*)d_in[12];
    float* out = (float*)d_out;

    float *p_x, *p_h2;
    __half *p_xpatch, *p_hn, *p_q, *p_k, *p_v, *p_ao, *p_t;
    __half *p_wconv, *p_wq, *p_wk, *p_wv, *p_wo, *p_wg, *p_wu, *p_wd;
    cudaGetSymbolAddress((void**)&p_x,  g_x);
    cudaGetSymbolAddress((void**)&p_h2, g_h2);
    cudaGetSymbolAddress((void**)&p_xpatch, a_xpatch);
    cudaGetSymbolAddress((void**)&p_hn, a_hn);
    cudaGetSymbolAddress((void**)&p_q,  a_q);
    cudaGetSymbolAddress((void**)&p_k,  a_k);
    cudaGetSymbolAddress((void**)&p_v,  a_v);
    cudaGetSymbolAddress((void**)&p_ao, a_ao);
    cudaGetSymbolAddress((void**)&p_t,  a_t);
    cudaGetSymbolAddress((void**)&p_wconv, h_wconv);
    cudaGetSymbolAddress((void**)&p_wq, h_wq);
    cudaGetSymbolAddress((void**)&p_wk, h_wk);
    cudaGetSymbolAddress((void**)&p_wv, h_wv);
    cudaGetSymbolAddress((void**)&p_wo, h_wo);
    cudaGetSymbolAddress((void**)&p_wg, h_wg);
    cudaGetSymbolAddress((void**)&p_wu, h_wu);
    cudaGetSymbolAddress((void**)&p_wd, h_wd);

    const int SMEM64  = 3 * (64 + 128) * SROWH * 2;   // 82944
    const int SMEMGU  = 3 * (64 + 256) * SROW2 * 2;   // 76800
    const int ASMEM   = 6 * 64 * SROWH * 2 + 64 * SP * 4 + 2 * 64 * 4;
    cudaFuncSetAttribute((const void*)gemm_f16<0, false>, cudaFuncAttributeMaxDynamicSharedMemorySize, SMEM64);
    cudaFuncSetAttribute((const void*)gemm_f16<1, false>, cudaFuncAttributeMaxDynamicSharedMemorySize, SMEM64);
    cudaFuncSetAttribute((const void*)gemm_qkv,           cudaFuncAttributeMaxDynamicSharedMemorySize, SMEM64);
    cudaFuncSetAttribute((const void*)gemm_gateup,        cudaFuncAttributeMaxDynamicSharedMemorySize, SMEMGU);
    cudaFuncSetAttribute((const void*)attn_mma_kernel,    cudaFuncAttributeMaxDynamicSharedMemorySize, ASMEM);

    // ---- side stream: batched weight conversion overlapped with compute ----
    cudaStream_t s2;
    cudaStreamCreateWithFlags(&s2, cudaStreamNonBlocking);
    cudaEvent_t evFork, evConv, evL[NLAYERS];
    cudaEventCreateWithFlags(&evFork, cudaEventDisableTiming);
    cudaEventCreateWithFlags(&evConv, cudaEventDisableTiming);
    for (int l = 0; l < NLAYERS; l++) cudaEventCreateWithFlags(&evL[l], cudaEventDisableTiming);

    cudaEventRecord(evFork, 0);
    cudaStreamWaitEvent(s2, evFork, 0);

    f2h_kernel<<<(HID * KPATCH / 16 + 255) / 256, 256, 0, s2>>>(conv_w, p_wconv, HID * KPATCH / 16);
    cudaEventRecord(evConv, s2);
    for (int l = 0; l < NLAYERS; l++) {
        size_t o1 = (size_t)l * HID * HID, o4 = (size_t)l * INTER * HID;
        f2h_batch<<<4096, 256, 0, s2>>>(
            q_w + o1, k_w + o1, v_w + o1, o_w + o1,
            gate_w + o4, up_w + o4, down_w + o4,
            p_wq + o1, p_wk + o1, p_wv + o1, p_wo + o1,
            p_wg + o4, p_wu + o4, p_wd + o4);
        cudaEventRecord(evL[l], s2);
    }

    dim3 grid_n1k(HID / 128, S_TOK / 64);       // (8, 24)
    dim3 grid_qkv(HID / 128, S_TOK / 64, 3);    // (8, 24, 3)
    dim3 grid_gu (INTER / 128, S_TOK / 64);     // (32, 24)

    prep_kernel<<<IM2COL_BLOCKS + S_TOK / 4, 256>>>(img0, img1);
    cudaStreamWaitEvent(0, evConv, 0);
    gemm_f16<0, false><<<grid_n1k, 256, SMEM64>>>(p_xpatch, p_wconv, nullptr, p_h2, HID, KPATCH);

    rms_kernel<false><<<S_TOK, 256>>>(p_h2, ln_pre_w, p_x);

    for (int l = 0; l < NLAYERS; l++) {
        const __half* qw = p_wq + (size_t)l * HID * HID;
        const __half* kw = p_wk + (size_t)l * HID * HID;
        const __half* vw = p_wv + (size_t)l * HID * HID;
        const __half* ow = p_wo + (size_t)l * HID * HID;
        const __half* gw = p_wg + (size_t)l * INTER * HID;
        const __half* uw = p_wu + (size_t)l * INTER * HID;
        const __half* dw = p_wd + (size_t)l * HID * INTER;

        rms_kernel<true><<<S_TOK, 256>>>(p_x, attn_norm_w + l * HID, p_hn);

        cudaStreamWaitEvent(0, evL[l], 0);   // layer-l weights ready

        gemm_qkv<<<grid_qkv, 256, SMEM64>>>(p_hn, qw, kw, vw, p_q, p_k, p_v, HID);

        attn_mma_kernel<<<dim3(S_TOK / 64, HEADS), 256, ASMEM>>>(p_q, p_k, p_v, p_ao);

        gemm_f16<1, false><<<grid_n1k, 256, SMEM64>>>(p_ao, ow, p_x, p_h2, HID, HID);

        rms_kernel<true><<<S_TOK, 256>>>(p_h2, ffn_norm_w + l * HID, p_hn);

        gemm_gateup<<<grid_gu, 256, SMEMGU>>>(p_hn, gw, uw, p_t, INTER, HID);

        float* dst = (l == NLAYERS - 1) ? out : p_x;
        gemm_f16<1, false><<<grid_n1k, 256, SMEM64>>>(p_t, dw, p_h2, dst, HID, INTER);
    }
    // streams/events intentionally not destroyed (active graph capture).
}

// round 14
// speedup vs baseline: 1.0144x; 1.0144x over previous
#include <cuda_runtime.h>
#include <cuda_fp16.h>
#include <math.h>
#include <stdint.h>

// ---------------- problem constants ----------------------------------------
#define S_TOK 1536
#define S0    1024
#define HID   1024
#define HEADS 16
#define HD    64
#define INTER 4096
#define NLAYERS 4
#define KPATCH 768

// ---------------- scratch ---------------------------------------------------
__device__ float g_x [S_TOK * HID];
__device__ float g_h2[S_TOK * HID];
__device__ float g_cos[S_TOK * HD];
__device__ float g_sin[S_TOK * HD];
__device__ __half a_xpatch[S_TOK * KPATCH];
__device__ __half a_hn[S_TOK * HID];
__device__ __half a_q [S_TOK * HID];
__device__ __half a_k [S_TOK * HID];
__device__ __half a_v [S_TOK * HID];
__device__ __half a_ao[S_TOK * HID];
__device__ __half a_t [S_TOK * INTER];
__device__ __half h_wconv[HID * KPATCH];
__device__ __half h_wq[NLAYERS * HID * HID];
__device__ __half h_wk[NLAYERS * HID * HID];
__device__ __half h_wv[NLAYERS * HID * HID];
__device__ __half h_wo[NLAYERS * HID * HID];
__device__ __half h_wg[NLAYERS * INTER * HID];
__device__ __half h_wu[NLAYERS * INTER * HID];
__device__ __half h_wd[NLAYERS * HID * INTER];

// ---------------- helpers ----------------------------------------------------
__device__ __forceinline__ uint32_t smem_u32(const void* p) {
    return (uint32_t)__cvta_generic_to_shared(p);
}
__device__ __forceinline__ void mma_f16(float c[4], const uint32_t a[4],
                                        uint32_t b0, uint32_t b1) {
    asm volatile(
        "mma.sync.aligned.m16n8k16.row.col.f32.f16.f16.f32 "
        "{%0,%1,%2,%3},{%4,%5,%6,%7},{%8,%9},{%0,%1,%2,%3};"
        : "+f"(c[0]), "+f"(c[1]), "+f"(c[2]), "+f"(c[3])
        : "r"(a[0]), "r"(a[1]), "r"(a[2]), "r"(a[3]), "r"(b0), "r"(b1));
}
__device__ __forceinline__ void ldm_x4(uint32_t& r0, uint32_t& r1, uint32_t& r2, uint32_t& r3,
                                       uint32_t addr) {
    asm volatile("ldmatrix.sync.aligned.m8n8.x4.shared.b16 {%0,%1,%2,%3}, [%4];"
                 : "=r"(r0), "=r"(r1), "=r"(r2), "=r"(r3) : "r"(addr));
}
__device__ __forceinline__ void ldm_x4t(uint32_t& r0, uint32_t& r1, uint32_t& r2, uint32_t& r3,
                                        uint32_t addr) {
    asm volatile("ldmatrix.sync.aligned.m8n8.x4.trans.shared.b16 {%0,%1,%2,%3}, [%4];"
                 : "=r"(r0), "=r"(r1), "=r"(r2), "=r"(r3) : "r"(addr));
}
__device__ __forceinline__ void cp16(void* smem_dst, const void* gsrc) {
    uint32_t d = (uint32_t)__cvta_generic_to_shared(smem_dst);
    asm volatile("cp.async.cg.shared.global [%0], [%1], 16;\n" :: "r"(d), "l"(gsrc));
}
#define CP_COMMIT() asm volatile("cp.async.commit_group;\n" ::: "memory")
#define CP_WAIT0()  asm volatile("cp.async.wait_group 0;\n" ::: "memory")
#define CP_WAIT1()  asm volatile("cp.async.wait_group 1;\n" ::: "memory")

// ---------------- weight fp32 -> fp16 ------------------------------------------
__global__ void f2h_kernel(const float* __restrict__ x, __half* __restrict__ y, int n16) {
    int i = blockIdx.x * blockDim.x + threadIdx.x;
    if (i >= n16) return;
    const float4* x4 = (const float4*)x;
    float4 v0 = x4[4 * i + 0];
    float4 v1 = x4[4 * i + 1];
    float4 v2 = x4[4 * i + 2];
    float4 v3 = x4[4 * i + 3];
    __half2 h0 = __floats2half2_rn(v0.x, v0.y), h1 = __floats2half2_rn(v0.z, v0.w);
    __half2 h2 = __floats2half2_rn(v1.x, v1.y), h3 = __floats2half2_rn(v1.z, v1.w);
    __half2 h4 = __floats2half2_rn(v2.x, v2.y), h5 = __floats2half2_rn(v2.z, v2.w);
    __half2 h6 = __floats2half2_rn(v3.x, v3.y), h7 = __floats2half2_rn(v3.z, v3.w);
    uint4 ua, ub;
    ua.x = *(uint32_t*)&h0; ua.y = *(uint32_t*)&h1;
    ua.z = *(uint32_t*)&h2; ua.w = *(uint32_t*)&h3;
    ub.x = *(uint32_t*)&h4; ub.y = *(uint32_t*)&h5;
    ub.z = *(uint32_t*)&h6; ub.w = *(uint32_t*)&h7;
    ((uint4*)y)[2 * i + 0] = ua;
    ((uint4*)y)[2 * i + 1] = ub;
}

// ---------------- im2col (fp16 out) --------------------------------------------
__global__ void im2col_kernel(const float* __restrict__ img0,
                              const float* __restrict__ img1) {
    int idx = blockIdx.x * blockDim.x + threadIdx.x;
    if (idx >= S_TOK * KPATCH) return;
    int s = idx / KPATCH;
    int r = idx - s * KPATCH;
    int c  = r >> 8;
    int kh = (r >> 4) & 15;
    int kw = r & 15;
    float val;
    if (s < S0) {
        int ph = s >> 5, pw = s & 31;
        val = img0[c * 512 * 512 + (ph * 16 + kh) * 512 + (pw * 16 + kw)];
    } else {
        int sp = s - S0;
        int ph = sp >> 4, pw = sp & 15;
        val = img1[c * 512 * 256 + (ph * 16 + kh) * 256 + (pw * 16 + kw)];
    }
    a_xpatch[idx] = __float2half(val);
}

// ---------------- RoPE table ----------------------------------------------------
__global__ void rope_table_kernel() {
    int s = blockIdx.x;
    int d = threadIdx.x;  // 0..63
    int ph, pw;
    if (s < S0) { ph = s >> 5; pw = s & 31; }
    else        { int sp = s - S0; ph = sp >> 4; pw = sp & 15; }
    int j = d & 31;
    float e, base;
    if (j < 16) { e = (4.0f * j) / 64.0f;               base = (float)ph; }
    else        { e = (2.0f + 4.0f * (j - 16)) / 64.0f; base = (float)pw; }
    float f = base * expf(-e * 9.2103403719761836f);
    g_cos[s * HD + d] = cosf(f);
    g_sin[s * HD + d] = sinf(f);
}

// ---------------- RMSNorm -------------------------------------------------------
template<bool OUT_HALF>
__global__ void rms_kernel(const float* __restrict__ x,
                           const float* __restrict__ w,
                           void* __restrict__ yv) {
    int s = blockIdx.x;
    int tid = threadIdx.x;  // 256
    const float* xr = x + s * HID;
    float ss = 0.f;
    #pragma unroll 4
    for (int i = tid; i < HID; i += 256) { float v = xr[i]; ss += v * v; }
    __shared__ float sh[8];
    #pragma unroll
    for (int o = 16; o > 0; o >>= 1) ss += __shfl_xor_sync(0xffffffffu, ss, o);
    if ((tid & 31) == 0) sh[tid >> 5] = ss;
    __syncthreads();
    if (tid < 8) {
        float v = sh[tid];
        #pragma unroll
        for (int o = 4; o > 0; o >>= 1) v += __shfl_xor_sync(0xffu, v, o);
        if (tid == 0) sh[0] = v;
    }
    __syncthreads();
    float r = rsqrtf(sh[0] * (1.0f / HID) + 1e-5f);
    if (OUT_HALF) {
        __half* y = (__half*)yv;
        for (int i = tid; i < HID; i += 256) y[s * HID + i] = __float2half(xr[i] * r * w[i]);
    } else {
        float* y = (float*)yv;
        for (int i = tid; i < HID; i += 256) y[s * HID + i] = xr[i] * r * w[i];
    }
}

#define SROWH 72   // halves per smem row (64 data + 8 pad)
#define SROW2 40   // halves per row for BK=32 (32 data + 8 pad)

// ---------------- fp16 GEMM core (64x128x64, 2m x 4n warps) --------------------
template<int EPI, bool OUT_HALF>
__device__ __forceinline__ void gemm_body(
    const __half* __restrict__ A, const __half* __restrict__ B,
    const void* __restrict__ auxp, void* __restrict__ Cp,
    int N, int K, __half* tiles)
{
    constexpr int BM = 64;
    constexpr int MT = 2;
    constexpr int ASTG = BM * SROWH;
    constexpr int BSTG = 128 * SROWH;
    constexpr int STG  = ASTG + BSTG;

    int tid = threadIdx.x;
    int warp = tid >> 5, lane = tid & 31;
    int gid = lane >> 2, tig = lane & 3;
    int g8 = lane >> 3, r8 = lane & 7;
    int wm = warp >> 2, wn = warp & 3;
    int m0 = blockIdx.y * BM, n0 = blockIdx.x * 128;

    float acc[MT][4][4];
    #pragma unroll
    for (int i = 0; i < MT; i++)
        #pragma unroll
        for (int j = 0; j < 4; j++)
            #pragma unroll
            for (int l = 0; l < 4; l++) acc[i][j][l] = 0.f;

    const int KT = K >> 6;
    constexpr int NCH = (BM + 128) * 8;

    auto load_stage = [&](int kt, int s) {
        int k0 = kt << 6;
        __half* As = tiles + s * STG;
        __half* Bs = As + ASTG;
        #pragma unroll
        for (int i = tid; i < NCH; i += 256) {
            int r = i >> 3, c = (i & 7) << 3;
            if (r < BM) cp16(&As[r * SROWH + c], &A[(size_t)(m0 + r) * K + k0 + c]);
            else {
                int rb = r - BM;
                cp16(&Bs[rb * SROWH + c], &B[(size_t)(n0 + rb) * K + k0 + c]);
            }
        }
        CP_COMMIT();
    };

    uint32_t a_off[MT], b_off[2];
    #pragma unroll
    for (int i = 0; i < MT; i++)
        a_off[i] = (uint32_t)(((wm * 32 + i * 16 + (g8 & 1) * 8 + r8) * SROWH) * 2
                              + (g8 >> 1) * 16);
    #pragma unroll
    for (int jj = 0; jj < 2; jj++)
        b_off[jj] = (uint32_t)(ASTG * 2 + ((wn * 32 + jj * 16 + (g8 >> 1) * 8 + r8) * SROWH) * 2
                               + (g8 & 1) * 16);

    load_stage(0, 0);
    load_stage(1, 1);

    for (int kt = 0; kt < KT; kt++) {
        int s = kt % 3;
        if (kt + 1 < KT) CP_WAIT1(); else CP_WAIT0();
        __syncthreads();
        if (kt + 2 < KT) load_stage(kt + 2, (kt + 2) % 3);
        uint32_t base = smem_u32(tiles + s * STG);
        #pragma unroll
        for (int ks = 0; ks < 4; ks++) {
            uint32_t kofs = base + ks * 32;
            uint32_t af[MT][4];
            #pragma unroll
            for (int i = 0; i < MT; i++)
                ldm_x4(af[i][0], af[i][1], af[i][2], af[i][3], kofs + a_off[i]);
            uint32_t bf[4][2];
            #pragma unroll
            for (int jj = 0; jj < 2; jj++) {
                uint32_t m0r, m1r, m2r, m3r;
                ldm_x4(m0r, m1r, m2r, m3r, kofs + b_off[jj]);
                bf[2 * jj + 0][0] = m0r; bf[2 * jj + 0][1] = m1r;
                bf[2 * jj + 1][0] = m2r; bf[2 * jj + 1][1] = m3r;
            }
            #pragma unroll
            for (int i = 0; i < MT; i++)
                #pragma unroll
                for (int j = 0; j < 4; j++)
                    mma_f16(acc[i][j], af[i], bf[j][0], bf[j][1]);
        }
    }

    const float* auxf = (const float*)auxp;
    #pragma unroll
    for (int i = 0; i < MT; i++) {
        #pragma unroll
        for (int j = 0; j < 4; j++) {
            int m = m0 + wm * 32 + i * 16 + gid;
            int n = n0 + wn * 32 + j * 8 + 2 * tig;
            #pragma unroll
            for (int hh = 0; hh < 2; hh++) {
                int mm = m + hh * 8;
                float v0 = acc[i][j][hh * 2 + 0];
                float v1 = acc[i][j][hh * 2 + 1];
                size_t off = (size_t)mm * N + n;
                if (EPI == 1) { v0 += auxf[off]; v1 += auxf[off + 1]; }
                if (OUT_HALF) {
                    *(__half2*)&((__half*)Cp)[off] = __floats2half2_rn(v0, v1);
                } else {
                    float2 o2; o2.x = v0; o2.y = v1;
                    *(float2*)&((float*)Cp)[off] = o2;
                }
            }
        }
    }
}

template<int EPI, bool OUT_HALF>
__global__ void __launch_bounds__(256) gemm_f16(
    const __half* __restrict__ A, const __half* __restrict__ B,
    const void* __restrict__ aux, void* __restrict__ C, int N, int K)
{
    extern __shared__ __half tiles[];
    gemm_body<EPI, OUT_HALF>(A, B, aux, C, N, K, tiles);
}

// ---------------- QKV GEMM with fused RoPE epilogue (coalesced stores) ----------
// z=0 -> Q (rope + 0.125), z=1 -> K (rope), z=2 -> V (plain).
#define CSR 136   // staging row stride (halves)

__global__ void __launch_bounds__(256) gemm_qkv(
    const __half* __restrict__ A,
    const __half* __restrict__ B0, const __half* __restrict__ B1, const __half* __restrict__ B2,
    __half* __restrict__ C0, __half* __restrict__ C1, __half* __restrict__ C2, int K)
{
    extern __shared__ __half tiles[];
    constexpr int BM = 64;
    constexpr int MT = 2;
    constexpr int ASTG = BM * SROWH;
    constexpr int BSTG = 128 * SROWH;
    constexpr int STG  = ASTG + BSTG;

    int zsel = blockIdx.z;
    const __half* B = (zsel == 0) ? B0 : (zsel == 1) ? B1 : B2;
    __half*       C = (zsel == 0) ? C0 : (zsel == 1) ? C1 : C2;

    int tid = threadIdx.x;
    int warp = tid >> 5, lane = tid & 31;
    int gid = lane >> 2, tig = lane & 3;
    int g8 = lane >> 3, r8 = lane & 7;
    int wm = warp >> 2, wn = warp & 3;
    int m0 = blockIdx.y * BM, n0 = blockIdx.x * 128;

    float acc[MT][4][4];
    #pragma unroll
    for (int i = 0; i < MT; i++)
        #pragma unroll
        for (int j = 0; j < 4; j++)
            #pragma unroll
            for (int l = 0; l < 4; l++) acc[i][j][l] = 0.f;

    const int KT = K >> 6;
    constexpr int NCH = (BM + 128) * 8;

    auto load_stage = [&](int kt, int s) {
        int k0 = kt << 6;
        __half* As = tiles + s * STG;
        __half* Bs = As + ASTG;
        #pragma unroll
        for (int i = tid; i < NCH; i += 256) {
            int r = i >> 3, c = (i & 7) << 3;
            if (r < BM) cp16(&As[r * SROWH + c], &A[(size_t)(m0 + r) * K + k0 + c]);
            else {
                int rb = r - BM;
                cp16(&Bs[rb * SROWH + c], &B[(size_t)(n0 + rb) * K + k0 + c]);
            }
        }
        CP_COMMIT();
    };

    uint32_t a_off[MT], b_off[2];
    #pragma unroll
    for (int i = 0; i < MT; i++)
        a_off[i] = (uint32_t)(((wm * 32 + i * 16 + (g8 & 1) * 8 + r8) * SROWH) * 2
                              + (g8 >> 1) * 16);
    #pragma unroll
    for (int jj = 0; jj < 2; jj++)
        b_off[jj] = (uint32_t)(ASTG * 2 + ((wn * 32 + jj * 16 + (g8 >> 1) * 8 + r8) * SROWH) * 2
                               + (g8 & 1) * 16);

    load_stage(0, 0);
    load_stage(1, 1);

    for (int kt = 0; kt < KT; kt++) {
        int s = kt % 3;
        if (kt + 1 < KT) CP_WAIT1(); else CP_WAIT0();
        __syncthreads();
        if (kt + 2 < KT) load_stage(kt + 2, (kt + 2) % 3);
        uint32_t base = smem_u32(tiles + s * STG);
        #pragma unroll
        for (int ks = 0; ks < 4; ks++) {
            uint32_t kofs = base + ks * 32;
            uint32_t af[MT][4];
            #pragma unroll
            for (int i = 0; i < MT; i++)
                ldm_x4(af[i][0], af[i][1], af[i][2], af[i][3], kofs + a_off[i]);
            uint32_t bf[4][2];
            #pragma unroll
            for (int jj = 0; jj < 2; jj++) {
                uint32_t m0r, m1r, m2r, m3r;
                ldm_x4(m0r, m1r, m2r, m3r, kofs + b_off[jj]);
                bf[2 * jj + 0][0] = m0r; bf[2 * jj + 0][1] = m1r;
                bf[2 * jj + 1][0] = m2r; bf[2 * jj + 1][1] = m3r;
            }
            #pragma unroll
            for (int i = 0; i < MT; i++)
                #pragma unroll
                for (int j = 0; j < 4; j++)
                    mma_f16(acc[i][j], af[i], bf[j][0], bf[j][1]);
        }
    }

    if (zsel < 2) {
        // stage tile in smem (half-rounded, matching the prior Q/K dataflow)
        __syncthreads();
        __half* Cs = tiles;
        #pragma unroll
        for (int i = 0; i < MT; i++)
            #pragma unroll
            for (int j = 0; j < 4; j++) {
                int rr = wm * 32 + i * 16 + gid;
                int cc = wn * 32 + j * 8 + 2 * tig;
                #pragma unroll
                for (int hh = 0; hh < 2; hh++)
                    *(__half2*)&Cs[(rr + hh * 8) * CSR + cc] =
                        __floats2half2_rn(acc[i][j][hh * 2], acc[i][j][hh * 2 + 1]);
            }
        __syncthreads();

        float qscale = (zsel == 0) ? 0.125f : 1.0f;
        // 512 items: row (64) x head (2) x d-block (4 of 8). 16B stores, coalesced.
        #pragma unroll
        for (int it = tid; it < 512; it += 256) {
            int r   = it >> 3;
            int sub = it & 7;
            int hh  = sub >> 2;
            int d0  = (sub & 3) * 8;
            int token = m0 + r;
            __half lo[8], hi[8];
            #pragma unroll
            for (int e = 0; e < 8; e++) {
                int d = d0 + e;
                float c  = g_cos[token * HD + d];
                float sn = g_sin[token * HD + d];
                float v0 = __half2float(Cs[r * CSR + hh * 64 + d]);
                float v1 = __half2float(Cs[r * CSR + hh * 64 + d + 32]);
                lo[e] = __float2half((v0 * c - v1 * sn) * qscale);
                hi[e] = __float2half((v1 * c + v0 * sn) * qscale);
            }
            size_t gb = (size_t)token * HID + n0 + hh * 64 + d0;
            *(uint4*)&C[gb]      = *(uint4*)lo;
            *(uint4*)&C[gb + 32] = *(uint4*)hi;
        }
    } else {
        #pragma unroll
        for (int i = 0; i < MT; i++)
            #pragma unroll
            for (int j = 0; j < 4; j++) {
                int m = m0 + wm * 32 + i * 16 + gid;
                int n = n0 + wn * 32 + j * 8 + 2 * tig;
                #pragma unroll
                for (int hh = 0; hh < 2; hh++) {
                    size_t off = (size_t)(m + hh * 8) * HID + n;
                    *(__half2*)&C[off] =
                        __floats2half2_rn(acc[i][j][hh * 2], acc[i][j][hh * 2 + 1]);
                }
            }
    }
}

// ---------------- fused gate||up GEMM (64x128x32) with SiLU ---------------------
__global__ void __launch_bounds__(256) gemm_gateup(
    const __half* __restrict__ A, const __half* __restrict__ G,
    const __half* __restrict__ U, __half* __restrict__ C, int N, int K)
{
    extern __shared__ __half tiles[];
    constexpr int BM = 64;
    constexpr int ASTG = BM * SROW2;
    constexpr int BSTG = 128 * SROW2;
    constexpr int STG  = ASTG + 2 * BSTG;

    int tid = threadIdx.x;
    int warp = tid >> 5, lane = tid & 31;
    int gid = lane >> 2, tig = lane & 3;
    int g8 = lane >> 3, r8 = lane & 7;
    int wm = warp >> 2, wn = warp & 3;
    int m0 = blockIdx.y * BM, n0 = blockIdx.x * 128;

    float accg[2][4][4], accu[2][4][4];
    #pragma unroll
    for (int i = 0; i < 2; i++)
        #pragma unroll
        for (int j = 0; j < 4; j++)
            #pragma unroll
            for (int l = 0; l < 4; l++) { accg[i][j][l] = 0.f; accu[i][j][l] = 0.f; }

    const int KT = K >> 5;
    constexpr int NCH = (BM + 256) * 4;

    auto load_stage = [&](int kt, int s) {
        int k0 = kt << 5;
        __half* As = tiles + s * STG;
        __half* Gs = As + ASTG;
        __half* Us = Gs + BSTG;
        #pragma unroll
        for (int i = tid; i < NCH; i += 256) {
            int r = i >> 2, c = (i & 3) << 3;
            if (r < BM) cp16(&As[r * SROW2 + c], &A[(size_t)(m0 + r) * K + k0 + c]);
            else if (r < BM + 128) {
                int rb = r - BM;
                cp16(&Gs[rb * SROW2 + c], &G[(size_t)(n0 + rb) * K + k0 + c]);
            } else {
                int rb = r - BM - 128;
                cp16(&Us[rb * SROW2 + c], &U[(size_t)(n0 + rb) * K + k0 + c]);
            }
        }
        CP_COMMIT();
    };

    uint32_t a_off[2], g_off[2], u_off[2];
    #pragma unroll
    for (int i = 0; i < 2; i++)
        a_off[i] = (uint32_t)(((wm * 32 + i * 16 + (g8 & 1) * 8 + r8) * SROW2) * 2
                              + (g8 >> 1) * 16);
    #pragma unroll
    for (int jj = 0; jj < 2; jj++) {
        uint32_t row = (uint32_t)(wn * 32 + jj * 16 + (g8 >> 1) * 8 + r8);
        g_off[jj] = (uint32_t)(ASTG * 2 + (row * SROW2) * 2 + (g8 & 1) * 16);
        u_off[jj] = g_off[jj] + BSTG * 2;
    }

    load_stage(0, 0);
    load_stage(1, 1);

    for (int kt = 0; kt < KT; kt++) {
        int s = kt % 3;
        if (kt + 1 < KT) CP_WAIT1(); else CP_WAIT0();
        __syncthreads();
        if (kt + 2 < KT) load_stage(kt + 2, (kt + 2) % 3);
        uint32_t base = smem_u32(tiles + s * STG);
        #pragma unroll
        for (int ks = 0; ks < 2; ks++) {
            uint32_t kofs = base + ks * 32;
            uint32_t af[2][4];
            #pragma unroll
            for (int i = 0; i < 2; i++)
                ldm_x4(af[i][0], af[i][1], af[i][2], af[i][3], kofs + a_off[i]);
            uint32_t gf[4][2], uf[4][2];
            #pragma unroll
            for (int jj = 0; jj < 2; jj++) {
                uint32_t m0r, m1r, m2r, m3r;
                ldm_x4(m0r, m1r, m2r, m3r, kofs + g_off[jj]);
                gf[2 * jj + 0][0] = m0r; gf[2 * jj + 0][1] = m1r;
                gf[2 * jj + 1][0] = m2r; gf[2 * jj + 1][1] = m3r;
                ldm_x4(m0r, m1r, m2r, m3r, kofs + u_off[jj]);
                uf[2 * jj + 0][0] = m0r; uf[2 * jj + 0][1] = m1r;
                uf[2 * jj + 1][0] = m2r; uf[2 * jj + 1][1] = m3r;
            }
            #pragma unroll
            for (int i = 0; i < 2; i++)
                #pragma unroll
                for (int j = 0; j < 4; j++) {
                    mma_f16(accg[i][j], af[i], gf[j][0], gf[j][1]);
                    mma_f16(accu[i][j], af[i], uf[j][0], uf[j][1]);
                }
        }
    }

    #pragma unroll
    for (int i = 0; i < 2; i++) {
        #pragma unroll
        for (int j = 0; j < 4; j++) {
            int m = m0 + wm * 32 + i * 16 + gid;
            int n = n0 + wn * 32 + j * 8 + 2 * tig;
            #pragma unroll
            for (int hh = 0; hh < 2; hh++) {
                int mm = m + hh * 8;
                float gg0 = accg[i][j][hh * 2 + 0], gg1 = accg[i][j][hh * 2 + 1];
                float v0 = accu[i][j][hh * 2 + 0] * gg0 / (1.0f + __expf(-gg0));
                float v1 = accu[i][j][hh * 2 + 1] * gg1 / (1.0f + __expf(-gg1));
                size_t off = (size_t)mm * N + n;
                *(__half2*)&C[off] = __floats2half2_rn(v0, v1);
            }
        }
    }
}

// ---------------- fp16 flash attention (double-buffered K/V) ---------------------
#define SP 68   // score row stride (floats)

__global__ void __launch_bounds__(256) attn_mma_kernel(
    const __half* __restrict__ q, const __half* __restrict__ k,
    const __half* __restrict__ v, __half* __restrict__ o)
{
    extern __shared__ char smraw[];
    __half* Qs = (__half*)smraw;
    __half* Kb = Qs + 64 * SROWH;
    __half* Vb = Kb + 2 * 64 * SROWH;
    __half* Ps = Vb + 2 * 64 * SROWH;
    float*  Ss = (float*)(Ps + 64 * SROWH);
    float*  Al = Ss + 64 * SP;
    float*  Ll = Al + 64;

    int qt = blockIdx.x, h = blockIdx.y;
    int s0 = qt * 64;
    int key0 = (s0 < S0) ? 0 : S0;
    int nkt  = (s0 < S0) ? 16 : 8;

    int tid = threadIdx.x;
    int warp = tid >> 5, lane = tid & 31;
    int gid = lane >> 2, tig = lane & 3;
    int g8 = lane >> 3, r8 = lane & 7;
    int wm = warp >> 1, wn = warp & 1;
    int qq = tid >> 2, kg = tid & 3;

    auto load_tile = [&](int kt) {
        __half* Kd = Kb + (kt & 1) * 64 * SROWH;
        __half* Vd = Vb + (kt & 1) * 64 * SROWH;
        for (int i = tid; i < 1024; i += 256) {
            int sel = i >> 9;
            int i2 = i & 511;
            int r = i2 >> 3, c = (i2 & 7) << 3;
            size_t g = (size_t)(key0 + kt * 64 + r) * HID + h * HD + c;
            if (sel == 0) cp16(&Kd[r * SROWH + c], &k[g]);
            else          cp16(&Vd[r * SROWH + c], &v[g]);
        }
        CP_COMMIT();
    };

    for (int i = tid; i < 512; i += 256) {
        int r = i >> 3, c = (i & 7) << 3;
        cp16(&Qs[r * SROWH + c], &q[(size_t)(s0 + r) * HID + h * HD + c]);
    }
    CP_COMMIT();
    load_tile(0);

    float m_prev = -1e30f, lsum = 0.f;
    float oacc[4][4];
    #pragma unroll
    for (int j = 0; j < 4; j++)
        #pragma unroll
        for (int l = 0; l < 4; l++) oacc[j][l] = 0.f;

    int arow0 = wm * 16 + gid;

    uint32_t qa_off = (uint32_t)(((wm * 16 + (g8 & 1) * 8 + r8) * SROWH) * 2 + (g8 >> 1) * 16);
    uint32_t kb_off[2];
    #pragma unroll
    for (int jj = 0; jj < 2; jj++)
        kb_off[jj] = (uint32_t)(((wn * 32 + jj * 16 + (g8 >> 1) * 8 + r8) * SROWH) * 2
                                + (g8 & 1) * 16);

    uint32_t qbase = smem_u32(Qs);
    uint32_t pbase = smem_u32(Ps);

    for (int kt = 0; kt < nkt; kt++) {
        CP_WAIT0();
        __syncthreads();
        if (kt + 1 < nkt) load_tile(kt + 1);

        uint32_t kbase = smem_u32(Kb + (kt & 1) * 64 * SROWH);
        uint32_t vbase = smem_u32(Vb + (kt & 1) * 64 * SROWH);

        float sc[4][4];
        #pragma unroll
        for (int j = 0; j < 4; j++)
            #pragma unroll
            for (int l = 0; l < 4; l++) sc[j][l] = 0.f;
        #pragma unroll
        for (int ks = 0; ks < 4; ks++) {
            uint32_t kofs = ks * 32;
            uint32_t aq[4];
            ldm_x4(aq[0], aq[1], aq[2], aq[3], qbase + kofs + qa_off);
            uint32_t bf[4][2];
            #pragma unroll
            for (int jj = 0; jj < 2; jj++) {
                uint32_t m0r, m1r, m2r, m3r;
                ldm_x4(m0r, m1r, m2r, m3r, kbase + kofs + kb_off[jj]);
                bf[2 * jj + 0][0] = m0r; bf[2 * jj + 0][1] = m1r;
                bf[2 * jj + 1][0] = m2r; bf[2 * jj + 1][1] = m3r;
            }
            #pragma unroll
            for (int j = 0; j < 4; j++)
                mma_f16(sc[j], aq, bf[j][0], bf[j][1]);
        }
        #pragma unroll
        for (int j = 0; j < 4; j++) {
            int cn = wn * 32 + j * 8 + 2 * tig;
            Ss[arow0 * SP + cn]           = sc[j][0];
            Ss[arow0 * SP + cn + 1]       = sc[j][1];
            Ss[(arow0 + 8) * SP + cn]     = sc[j][2];
            Ss[(arow0 + 8) * SP + cn + 1] = sc[j][3];
        }
        __syncthreads();

        {
            float e[16];
            int base = qq * SP + kg * 16;
            float mloc = -1e30f;
            #pragma unroll
            for (int i = 0; i < 16; i++) { e[i] = Ss[base + i]; mloc = fmaxf(mloc, e[i]); }
            mloc = fmaxf(mloc, __shfl_xor_sync(0xffffffffu, mloc, 1));
            mloc = fmaxf(mloc, __shfl_xor_sync(0xffffffffu, mloc, 2));
            float m_new = fmaxf(m_prev, mloc);
            float alpha = __expf(m_prev - m_new);
            float lrow = 0.f;
            int pb = qq * SROWH + kg * 16;
            #pragma unroll
            for (int i = 0; i < 16; i += 2) {
                float e0 = __expf(e[i]     - m_new);
                float e1 = __expf(e[i + 1] - m_new);
                lrow += e0 + e1;
                *(__half2*)&Ps[pb + i] = __floats2half2_rn(e0, e1);
            }
            lrow += __shfl_xor_sync(0xffffffffu, lrow, 1);
            lrow += __shfl_xor_sync(0xffffffffu, lrow, 2);
            lsum = lsum * alpha + lrow;
            m_prev = m_new;
            if (kg == 0) Al[qq] = alpha;
        }
        __syncthreads();

        float a_r0 = Al[arow0], a_r1 = Al[arow0 + 8];
        #pragma unroll
        for (int j = 0; j < 4; j++) {
            oacc[j][0] *= a_r0; oacc[j][1] *= a_r0;
            oacc[j][2] *= a_r1; oacc[j][3] *= a_r1;
        }

        #pragma unroll
        for (int ks = 0; ks < 4; ks++) {
            uint32_t ap[4];
            ldm_x4(ap[0], ap[1], ap[2], ap[3], pbase + ks * 32 + qa_off);
            uint32_t vf[4][2];
            #pragma unroll
            for (int jj = 0; jj < 2; jj++) {
                uint32_t addr = vbase
                    + (uint32_t)(((ks * 16 + (g8 & 1) * 8 + r8) * SROWH) * 2
                                 + (wn * 32 + jj * 16) * 2 + (g8 >> 1) * 16);
                uint32_t m0r, m1r, m2r, m3r;
                ldm_x4t(m0r, m1r, m2r, m3r, addr);
                vf[2 * jj + 0][0] = m0r; vf[2 * jj + 0][1] = m1r;
                vf[2 * jj + 1][0] = m2r; vf[2 * jj + 1][1] = m3r;
            }
            #pragma unroll
            for (int j = 0; j < 4; j++)
                mma_f16(oacc[j], ap, vf[j][0], vf[j][1]);
        }
        __syncthreads();
    }

    if (kg == 0) Ll[qq] = lsum;
    __syncthreads();
    float inv0 = 1.0f / Ll[arow0];
    float inv1 = 1.0f / Ll[arow0 + 8];
    #pragma unroll
    for (int j = 0; j < 4; j++) {
        int cn = wn * 32 + j * 8 + 2 * tig;
        size_t o0 = (size_t)(s0 + arow0) * HID + h * HD + cn;
        size_t o1 = (size_t)(s0 + arow0 + 8) * HID + h * HD + cn;
        *(__half2*)&o[o0] = __floats2half2_rn(oacc[j][0] * inv0, oacc[j][1] * inv0);
        *(__half2*)&o[o1] = __floats2half2_rn(oacc[j][2] * inv1, oacc[j][3] * inv1);
    }
}

// ---------------- host orchestration ---------------------------------------------
extern "C" void kernel_launch(void* const* d_in, const int* in_sizes, int n_in,
                              void* d_out, int out_size) {
    const float* img0        = (const float*)d_in[0];
    const float* img1        = (const float*)d_in[1];
    const float* conv_w      = (const float*)d_in[2];
    const float* ln_pre_w    = (const float*)d_in[3];
    const float* attn_norm_w = (const float*)d_in[4];
    const float* q_w         = (const float*)d_in[5];
    const float* k_w         = (const float*)d_in[6];
    const float* v_w         = (const float*)d_in[7];
    const float* o_w         = (const float*)d_in[8];
    const float* ffn_norm_w  = (const float*)d_in[9];
    const float* gate_w      = (const float*)d_in[10];
    const float* up_w        = (const float*)d_in[11];
    const float* down_w      = (const float*)d_in[12];
    float* out = (float*)d_out;

    float *p_x, *p_h2;
    __half *p_xpatch, *p_hn, *p_q, *p_k, *p_v, *p_ao, *p_t;
    __half *p_wconv, *p_wq, *p_wk, *p_wv, *p_wo, *p_wg, *p_wu, *p_wd;
    cudaGetSymbolAddress((void**)&p_x,  g_x);
    cudaGetSymbolAddress((void**)&p_h2, g_h2);
    cudaGetSymbolAddress((void**)&p_xpatch, a_xpatch);
    cudaGetSymbolAddress((void**)&p_hn, a_hn);
    cudaGetSymbolAddress((void**)&p_q,  a_q);
    cudaGetSymbolAddress((void**)&p_k,  a_k);
    cudaGetSymbolAddress((void**)&p_v,  a_v);
    cudaGetSymbolAddress((void**)&p_ao, a_ao);
    cudaGetSymbolAddress((void**)&p_t,  a_t);
    cudaGetSymbolAddress((void**)&p_wconv, h_wconv);
    cudaGetSymbolAddress((void**)&p_wq, h_wq);
    cudaGetSymbolAddress((void**)&p_wk, h_wk);
    cudaGetSymbolAddress((void**)&p_wv, h_wv);
    cudaGetSymbolAddress((void**)&p_wo, h_wo);
    cudaGetSymbolAddress((void**)&p_wg, h_wg);
    cudaGetSymbolAddress((void**)&p_wu, h_wu);
    cudaGetSymbolAddress((void**)&p_wd, h_wd);

    const int SMEM64  = 3 * (64 + 128) * SROWH * 2;   // 82944
    const int SMEMGU  = 3 * (64 + 256) * SROW2 * 2;   // 76800
    const int ASMEM   = 6 * 64 * SROWH * 2 + 64 * SP * 4 + 2 * 64 * 4;
    cudaFuncSetAttribute((const void*)gemm_f16<0, false>, cudaFuncAttributeMaxDynamicSharedMemorySize, SMEM64);
    cudaFuncSetAttribute((const void*)gemm_f16<1, false>, cudaFuncAttributeMaxDynamicSharedMemorySize, SMEM64);
    cudaFuncSetAttribute((const void*)gemm_qkv,           cudaFuncAttributeMaxDynamicSharedMemorySize, SMEM64);
    cudaFuncSetAttribute((const void*)gemm_gateup,        cudaFuncAttributeMaxDynamicSharedMemorySize, SMEMGU);
    cudaFuncSetAttribute((const void*)attn_mma_kernel,    cudaFuncAttributeMaxDynamicSharedMemorySize, ASMEM);

    // ---- side stream: per-weight f2h (R9 granularity) overlapped with compute ----
    cudaStream_t s2;
    cudaStreamCreateWithFlags(&s2, cudaStreamNonBlocking);
    cudaEvent_t evFork, evConv, evL[NLAYERS];
    cudaEventCreateWithFlags(&evFork, cudaEventDisableTiming);
    cudaEventCreateWithFlags(&evConv, cudaEventDisableTiming);
    for (int l = 0; l < NLAYERS; l++) cudaEventCreateWithFlags(&evL[l], cudaEventDisableTiming);

    cudaEventRecord(evFork, 0);
    cudaStreamWaitEvent(s2, evFork, 0);

    auto cvt = [&](const float* src, __half* dst, int n) {
        f2h_kernel<<<(n / 16 + 255) / 256, 256, 0, s2>>>(src, dst, n / 16);
    };
    cvt(conv_w, p_wconv, HID * KPATCH);
    cudaEventRecord(evConv, s2);
    for (int l = 0; l < NLAYERS; l++) {
        cvt(q_w    + (size_t)l * HID * HID,   p_wq + (size_t)l * HID * HID,   HID * HID);
        cvt(k_w    + (size_t)l * HID * HID,   p_wk + (size_t)l * HID * HID,   HID * HID);
        cvt(v_w    + (size_t)l * HID * HID,   p_wv + (size_t)l * HID * HID,   HID * HID);
        cvt(o_w    + (size_t)l * HID * HID,   p_wo + (size_t)l * HID * HID,   HID * HID);
        cvt(gate_w + (size_t)l * INTER * HID, p_wg + (size_t)l * INTER * HID, INTER * HID);
        cvt(up_w   + (size_t)l * INTER * HID, p_wu + (size_t)l * INTER * HID, INTER * HID);
        cvt(down_w + (size_t)l * HID * INTER, p_wd + (size_t)l * HID * INTER, HID * INTER);
        cudaEventRecord(evL[l], s2);
    }

    dim3 grid_n1k(HID / 128, S_TOK / 64);       // (8, 24)
    dim3 grid_qkv(HID / 128, S_TOK / 64, 3);    // (8, 24, 3)
    dim3 grid_gu (INTER / 128, S_TOK / 64);     // (32, 24)

    im2col_kernel<<<(S_TOK * KPATCH + 255) / 256, 256>>>(img0, img1);
    rope_table_kernel<<<S_TOK, 64>>>();
    cudaStreamWaitEvent(0, evConv, 0);
    gemm_f16<0, false><<<grid_n1k, 256, SMEM64>>>(p_xpatch, p_wconv, nullptr, p_h2, HID, KPATCH);

    rms_kernel<false><<<S_TOK, 256>>>(p_h2, ln_pre_w, p_x);

    for (int l = 0; l < NLAYERS; l++) {
        const __half* qw = p_wq + (size_t)l * HID * HID;
        const __half* kw = p_wk + (size_t)l * HID * HID;
        const __half* vw = p_wv + (size_t)l * HID * HID;
        const __half* ow = p_wo + (size_t)l * HID * HID;
        const __half* gw = p_wg + (size_t)l * INTER * HID;
        const __half* uw = p_wu + (size_t)l * INTER * HID;
        const __half* dw = p_wd + (size_t)l * HID * INTER;

        rms_kernel<true><<<S_TOK, 256>>>(p_x, attn_norm_w + l * HID, p_hn);

        cudaStreamWaitEvent(0, evL[l], 0);   // layer-l weights ready

        gemm_qkv<<<grid_qkv, 256, SMEM64>>>(p_hn, qw, kw, vw, p_q, p_k, p_v, HID);

        attn_mma_kernel<<<dim3(S_TOK / 64, HEADS), 256, ASMEM>>>(p_q, p_k, p_v, p_ao);

        gemm_f16<1, false><<<grid_n1k, 256, SMEM64>>>(p_ao, ow, p_x, p_h2, HID, HID);

        rms_kernel<true><<<S_TOK, 256>>>(p_h2, ffn_norm_w + l * HID, p_hn);

        gemm_gateup<<<grid_gu, 256, SMEMGU>>>(p_hn, gw, uw, p_t, INTER, HID);

        float* dst = (l == NLAYERS - 1) ? out : p_x;
        gemm_f16<1, false><<<grid_n1k, 256, SMEM64>>>(p_t, dw, p_h2, dst, HID, INTER);
    }
    // streams/events intentionally not destroyed (active graph capture).
}

// round 15
// speedup vs baseline: 1.0274x; 1.0128x over previous
#include <cuda_runtime.h>
#include <cuda_fp16.h>
#include <math.h>
#include <stdint.h>

// ---------------- problem constants ----------------------------------------
#define S_TOK 1536
#define S0    1024
#define HID   1024
#define HEADS 16
#define HD    64
#define INTER 4096
#define NLAYERS 4
#define KPATCH 768

// ---------------- scratch ---------------------------------------------------
__device__ float g_x [S_TOK * HID];
__device__ float g_h2[S_TOK * HID];
__device__ float g_cos[S_TOK * HD];
__device__ float g_sin[S_TOK * HD];
__device__ float g_pa[8 * S_TOK];   // partial sumsq for attn-rms (per n-block)
__device__ float g_pf[8 * S_TOK];   // partial sumsq for ffn-rms
__device__ __half a_xpatch[S_TOK * KPATCH];
__device__ __half a_x [S_TOK * HID];    // half copy of x  (attn-rms input)
__device__ __half a_x2[S_TOK * HID];    // half copy of h2 (ffn-rms input)
__device__ __half a_q [S_TOK * HID];
__device__ __half a_k [S_TOK * HID];
__device__ __half a_v [S_TOK * HID];
__device__ __half a_ao[S_TOK * HID];
__device__ __half a_t [S_TOK * INTER];
__device__ __half h_wconv[HID * KPATCH];
__device__ __half h_wq[NLAYERS * HID * HID];
__device__ __half h_wk[NLAYERS * HID * HID];
__device__ __half h_wv[NLAYERS * HID * HID];
__device__ __half h_wo[NLAYERS * HID * HID];
__device__ __half h_wg[NLAYERS * INTER * HID];
__device__ __half h_wu[NLAYERS * INTER * HID];
__device__ __half h_wd[NLAYERS * HID * INTER];

// ---------------- helpers ----------------------------------------------------
__device__ __forceinline__ uint32_t smem_u32(const void* p) {
    return (uint32_t)__cvta_generic_to_shared(p);
}
__device__ __forceinline__ void mma_f16(float c[4], const uint32_t a[4],
                                        uint32_t b0, uint32_t b1) {
    asm volatile(
        "mma.sync.aligned.m16n8k16.row.col.f32.f16.f16.f32 "
        "{%0,%1,%2,%3},{%4,%5,%6,%7},{%8,%9},{%0,%1,%2,%3};"
        : "+f"(c[0]), "+f"(c[1]), "+f"(c[2]), "+f"(c[3])
        : "r"(a[0]), "r"(a[1]), "r"(a[2]), "r"(a[3]), "r"(b0), "r"(b1));
}
__device__ __forceinline__ void ldm_x4(uint32_t& r0, uint32_t& r1, uint32_t& r2, uint32_t& r3,
                                       uint32_t addr) {
    asm volatile("ldmatrix.sync.aligned.m8n8.x4.shared.b16 {%0,%1,%2,%3}, [%4];"
                 : "=r"(r0), "=r"(r1), "=r"(r2), "=r"(r3) : "r"(addr));
}
__device__ __forceinline__ void ldm_x4t(uint32_t& r0, uint32_t& r1, uint32_t& r2, uint32_t& r3,
                                        uint32_t addr) {
    asm volatile("ldmatrix.sync.aligned.m8n8.x4.trans.shared.b16 {%0,%1,%2,%3}, [%4];"
                 : "=r"(r0), "=r"(r1), "=r"(r2), "=r"(r3) : "r"(addr));
}
__device__ __forceinline__ void cp16(void* smem_dst, const void* gsrc) {
    uint32_t d = (uint32_t)__cvta_generic_to_shared(smem_dst);
    asm volatile("cp.async.cg.shared.global [%0], [%1], 16;\n" :: "r"(d), "l"(gsrc));
}
#define CP_COMMIT() asm volatile("cp.async.commit_group;\n" ::: "memory")
#define CP_WAIT0()  asm volatile("cp.async.wait_group 0;\n" ::: "memory")
#define CP_WAIT1()  asm volatile("cp.async.wait_group 1;\n" ::: "memory")

// ---------------- weight fp32 -> fp16 (plain) ----------------------------------
__global__ void f2h_kernel(const float* __restrict__ x, __half* __restrict__ y, int n16) {
    int i = blockIdx.x * blockDim.x + threadIdx.x;
    if (i >= n16) return;
    const float4* x4 = (const float4*)x;
    float4 v0 = x4[4 * i + 0];
    float4 v1 = x4[4 * i + 1];
    float4 v2 = x4[4 * i + 2];
    float4 v3 = x4[4 * i + 3];
    __half2 h0 = __floats2half2_rn(v0.x, v0.y), h1 = __floats2half2_rn(v0.z, v0.w);
    __half2 h2 = __floats2half2_rn(v1.x, v1.y), h3 = __floats2half2_rn(v1.z, v1.w);
    __half2 h4 = __floats2half2_rn(v2.x, v2.y), h5 = __floats2half2_rn(v2.z, v2.w);
    __half2 h6 = __floats2half2_rn(v3.x, v3.y), h7 = __floats2half2_rn(v3.z, v3.w);
    uint4 ua, ub;
    ua.x = *(uint32_t*)&h0; ua.y = *(uint32_t*)&h1;
    ua.z = *(uint32_t*)&h2; ua.w = *(uint32_t*)&h3;
    ub.x = *(uint32_t*)&h4; ub.y = *(uint32_t*)&h5;
    ub.z = *(uint32_t*)&h6; ub.w = *(uint32_t*)&h7;
    ((uint4*)y)[2 * i + 0] = ua;
    ((uint4*)y)[2 * i + 1] = ub;
}

// ---------------- weight fp32 -> fp16 with rms-norm weight folded (K=1024) ------
__global__ void f2h_norm_kernel(const float* __restrict__ x, const float* __restrict__ nw,
                                __half* __restrict__ y, int n16) {
    int i = blockIdx.x * blockDim.x + threadIdx.x;
    if (i >= n16) return;
    int kb = (16 * i) & 1023;
    const float4* x4 = (const float4*)x;
    const float4* w4 = (const float4*)(nw + kb);
    float4 v0 = x4[4 * i + 0], w0 = w4[0];
    float4 v1 = x4[4 * i + 1], w1 = w4[1];
    float4 v2 = x4[4 * i + 2], w2 = w4[2];
    float4 v3 = x4[4 * i + 3], w3 = w4[3];
    __half2 h0 = __floats2half2_rn(v0.x * w0.x, v0.y * w0.y);
    __half2 h1 = __floats2half2_rn(v0.z * w0.z, v0.w * w0.w);
    __half2 h2 = __floats2half2_rn(v1.x * w1.x, v1.y * w1.y);
    __half2 h3 = __floats2half2_rn(v1.z * w1.z, v1.w * w1.w);
    __half2 h4 = __floats2half2_rn(v2.x * w2.x, v2.y * w2.y);
    __half2 h5 = __floats2half2_rn(v2.z * w2.z, v2.w * w2.w);
    __half2 h6 = __floats2half2_rn(v3.x * w3.x, v3.y * w3.y);
    __half2 h7 = __floats2half2_rn(v3.z * w3.z, v3.w * w3.w);
    uint4 ua, ub;
    ua.x = *(uint32_t*)&h0; ua.y = *(uint32_t*)&h1;
    ua.z = *(uint32_t*)&h2; ua.w = *(uint32_t*)&h3;
    ub.x = *(uint32_t*)&h4; ub.y = *(uint32_t*)&h5;
    ub.z = *(uint32_t*)&h6; ub.w = *(uint32_t*)&h7;
    ((uint4*)y)[2 * i + 0] = ua;
    ((uint4*)y)[2 * i + 1] = ub;
}

// ---------------- im2col (fp16 out) --------------------------------------------
__global__ void im2col_kernel(const float* __restrict__ img0,
                              const float* __restrict__ img1) {
    int idx = blockIdx.x * blockDim.x + threadIdx.x;
    if (idx >= S_TOK * KPATCH) return;
    int s = idx / KPATCH;
    int r = idx - s * KPATCH;
    int c  = r >> 8;
    int kh = (r >> 4) & 15;
    int kw = r & 15;
    float val;
    if (s < S0) {
        int ph = s >> 5, pw = s & 31;
        val = img0[c * 512 * 512 + (ph * 16 + kh) * 512 + (pw * 16 + kw)];
    } else {
        int sp = s - S0;
        int ph = sp >> 4, pw = sp & 15;
        val = img1[c * 512 * 256 + (ph * 16 + kh) * 256 + (pw * 16 + kw)];
    }
    a_xpatch[idx] = __float2half(val);
}

// ---------------- RoPE table ----------------------------------------------------
__global__ void rope_table_kernel() {
    int s = blockIdx.x;
    int d = threadIdx.x;  // 0..63
    int ph, pw;
    if (s < S0) { ph = s >> 5; pw = s & 31; }
    else        { int sp = s - S0; ph = sp >> 4; pw = sp & 15; }
    int j = d & 31;
    float e, base;
    if (j < 16) { e = (4.0f * j) / 64.0f;               base = (float)ph; }
    else        { e = (2.0f + 4.0f * (j - 16)) / 64.0f; base = (float)pw; }
    float f = base * expf(-e * 9.2103403719761836f);
    g_cos[s * HD + d] = cosf(f);
    g_sin[s * HD + d] = sinf(f);
}

// ---------------- ln_pre: rms + emit half copy + sumsq partials -----------------
__global__ void lnpre_kernel(const float* __restrict__ h2,
                             const float* __restrict__ w,
                             float* __restrict__ x,
                             __half* __restrict__ xh,
                             float* __restrict__ part) {
    int s = blockIdx.x;
    int tid = threadIdx.x;  // 256
    const float* xr = h2 + s * HID;
    float ss = 0.f;
    #pragma unroll 4
    for (int i = tid; i < HID; i += 256) { float v = xr[i]; ss += v * v; }
    __shared__ float sh[8];
    #pragma unroll
    for (int o = 16; o > 0; o >>= 1) ss += __shfl_xor_sync(0xffffffffu, ss, o);
    if ((tid & 31) == 0) sh[tid >> 5] = ss;
    __syncthreads();
    if (tid < 8) {
        float v = sh[tid];
        #pragma unroll
        for (int o = 4; o > 0; o >>= 1) v += __shfl_xor_sync(0xffu, v, o);
        if (tid == 0) sh[0] = v;
    }
    __syncthreads();
    float r = rsqrtf(sh[0] * (1.0f / HID) + 1e-5f);
    __syncthreads();   // sh[0] consumed; reuse below
    float ss2 = 0.f;
    for (int i = tid; i < HID; i += 256) {
        float v = xr[i] * r * w[i];
        x[s * HID + i] = v;
        xh[s * HID + i] = __float2half(v);
        ss2 += v * v;
    }
    #pragma unroll
    for (int o = 16; o > 0; o >>= 1) ss2 += __shfl_xor_sync(0xffffffffu, ss2, o);
    if ((tid & 31) == 0) sh[tid >> 5] = ss2;
    __syncthreads();
    if (tid < 8) {
        float v = sh[tid];
        #pragma unroll
        for (int o = 4; o > 0; o >>= 1) v += __shfl_xor_sync(0xffu, v, o);
        if (tid == 0) part[s] = v;          // slot 0
    }
    if (tid >= 8 && tid < 15) part[(tid - 7) * S_TOK + s] = 0.f;  // slots 1..7
    if (tid == 15) part[0 * S_TOK + s] += 0.f;  // no-op keep shape
    if (tid >= 16 && tid < 17) {}  // (nothing)
    if (tid == 17) {}
    // slots 1..7 zeroed above (tid 8..14 -> slots 1..7)
}

#define SROWH 72   // halves per smem row (64 data + 8 pad)
#define SROW2 40   // halves per row for BK=32 (32 data + 8 pad)

// ---------------- fp16 GEMM core (64x128x64, 2m x 4n warps) --------------------
// EPI: 0=plain, 1=+aux(fp32 residual)
// EMIT: 1 -> also write half copy of output (xh) and per-(CTA,row) sumsq partials.
template<int EPI, bool OUT_HALF, int EMIT>
__device__ __forceinline__ void gemm_body(
    const __half* __restrict__ A, const __half* __restrict__ B,
    const void* __restrict__ auxp, void* __restrict__ Cp,
    __half* __restrict__ xh, float* __restrict__ part,
    int N, int K, __half* tiles)
{
    constexpr int BM = 64;
    constexpr int MT = 2;
    constexpr int ASTG = BM * SROWH;
    constexpr int BSTG = 128 * SROWH;
    constexpr int STG  = ASTG + BSTG;

    int tid = threadIdx.x;
    int warp = tid >> 5, lane = tid & 31;
    int gid = lane >> 2, tig = lane & 3;
    int g8 = lane >> 3, r8 = lane & 7;
    int wm = warp >> 2, wn = warp & 3;
    int m0 = blockIdx.y * BM, n0 = blockIdx.x * 128;

    float acc[MT][4][4];
    #pragma unroll
    for (int i = 0; i < MT; i++)
        #pragma unroll
        for (int j = 0; j < 4; j++)
            #pragma unroll
            for (int l = 0; l < 4; l++) acc[i][j][l] = 0.f;

    const int KT = K >> 6;
    constexpr int NCH = (BM + 128) * 8;

    auto load_stage = [&](int kt, int s) {
        int k0 = kt << 6;
        __half* As = tiles + s * STG;
        __half* Bs = As + ASTG;
        #pragma unroll
        for (int i = tid; i < NCH; i += 256) {
            int r = i >> 3, c = (i & 7) << 3;
            if (r < BM) cp16(&As[r * SROWH + c], &A[(size_t)(m0 + r) * K + k0 + c]);
            else {
                int rb = r - BM;
                cp16(&Bs[rb * SROWH + c], &B[(size_t)(n0 + rb) * K + k0 + c]);
            }
        }
        CP_COMMIT();
    };

    uint32_t a_off[MT], b_off[2];
    #pragma unroll
    for (int i = 0; i < MT; i++)
        a_off[i] = (uint32_t)(((wm * 32 + i * 16 + (g8 & 1) * 8 + r8) * SROWH) * 2
                              + (g8 >> 1) * 16);
    #pragma unroll
    for (int jj = 0; jj < 2; jj++)
        b_off[jj] = (uint32_t)(ASTG * 2 + ((wn * 32 + jj * 16 + (g8 >> 1) * 8 + r8) * SROWH) * 2
                               + (g8 & 1) * 16);

    load_stage(0, 0);
    load_stage(1, 1);

    for (int kt = 0; kt < KT; kt++) {
        int s = kt % 3;
        if (kt + 1 < KT) CP_WAIT1(); else CP_WAIT0();
        __syncthreads();
        if (kt + 2 < KT) load_stage(kt + 2, (kt + 2) % 3);
        uint32_t base = smem_u32(tiles + s * STG);
        #pragma unroll
        for (int ks = 0; ks < 4; ks++) {
            uint32_t kofs = base + ks * 32;
            uint32_t af[MT][4];
            #pragma unroll
            for (int i = 0; i < MT; i++)
                ldm_x4(af[i][0], af[i][1], af[i][2], af[i][3], kofs + a_off[i]);
            uint32_t bf[4][2];
            #pragma unroll
            for (int jj = 0; jj < 2; jj++) {
                uint32_t m0r, m1r, m2r, m3r;
                ldm_x4(m0r, m1r, m2r, m3r, kofs + b_off[jj]);
                bf[2 * jj + 0][0] = m0r; bf[2 * jj + 0][1] = m1r;
                bf[2 * jj + 1][0] = m2r; bf[2 * jj + 1][1] = m3r;
            }
            #pragma unroll
            for (int i = 0; i < MT; i++)
                #pragma unroll
                for (int j = 0; j < 4; j++)
                    mma_f16(acc[i][j], af[i], bf[j][0], bf[j][1]);
        }
    }

    const float* auxf = (const float*)auxp;
    float ssq[2][2] = {{0.f, 0.f}, {0.f, 0.f}};
    #pragma unroll
    for (int i = 0; i < MT; i++) {
        #pragma unroll
        for (int j = 0; j < 4; j++) {
            int m = m0 + wm * 32 + i * 16 + gid;
            int n = n0 + wn * 32 + j * 8 + 2 * tig;
            #pragma unroll
            for (int hh = 0; hh < 2; hh++) {
                int mm = m + hh * 8;
                float v0 = acc[i][j][hh * 2 + 0];
                float v1 = acc[i][j][hh * 2 + 1];
                size_t off = (size_t)mm * N + n;
                if (EPI == 1) { v0 += auxf[off]; v1 += auxf[off + 1]; }
                if (OUT_HALF) {
                    *(__half2*)&((__half*)Cp)[off] = __floats2half2_rn(v0, v1);
                } else {
                    float2 o2; o2.x = v0; o2.y = v1;
                    *(float2*)&((float*)Cp)[off] = o2;
                }
                if (EMIT) {
                    *(__half2*)&xh[off] = __floats2half2_rn(v0, v1);
                    ssq[i][hh] += v0 * v0 + v1 * v1;
                }
            }
        }
    }

    if (EMIT) {
        // reduce across the 4 lanes of each row-group (same gid, tig 0..3)
        #pragma unroll
        for (int i = 0; i < 2; i++)
            #pragma unroll
            for (int hh = 0; hh < 2; hh++) {
                ssq[i][hh] += __shfl_xor_sync(0xffffffffu, ssq[i][hh], 1);
                ssq[i][hh] += __shfl_xor_sync(0xffffffffu, ssq[i][hh], 2);
            }
        __syncthreads();            // safe to reuse tile smem
        float* sw = (float*)tiles;  // [4 wn][64 rows]
        if (tig == 0) {
            #pragma unroll
            for (int i = 0; i < 2; i++)
                #pragma unroll
                for (int hh = 0; hh < 2; hh++)
                    sw[wn * 64 + wm * 32 + i * 16 + gid + hh * 8] = ssq[i][hh];
        }
        __syncthreads();
        if (tid < 64)
            part[blockIdx.x * S_TOK + m0 + tid] =
                sw[tid] + sw[64 + tid] + sw[128 + tid] + sw[192 + tid];
    }
}

template<int EPI, bool OUT_HALF, int EMIT>
__global__ void __launch_bounds__(256) gemm_f16(
    const __half* __restrict__ A, const __half* __restrict__ B,
    const void* __restrict__ aux, void* __restrict__ C,
    __half* __restrict__ xh, float* __restrict__ part, int N, int K)
{
    extern __shared__ __half tiles[];
    gemm_body<EPI, OUT_HALF, EMIT>(A, B, aux, C, xh, part, N, K, tiles);
}

// ---------------- QKV GEMM: rms-scale epilogue + fused RoPE ---------------------
// A = half(x) un-normalized; norm weight folded into B; r applied to accumulators.
// z=0 -> Q (rope + 0.125), z=1 -> K (rope), z=2 -> V (plain).
#define CSR 136

__global__ void __launch_bounds__(256) gemm_qkv(
    const __half* __restrict__ A,
    const __half* __restrict__ B0, const __half* __restrict__ B1, const __half* __restrict__ B2,
    __half* __restrict__ C0, __half* __restrict__ C1, __half* __restrict__ C2,
    const float* __restrict__ part, int K)
{
    extern __shared__ __half tiles[];
    __shared__ float rs[64];
    constexpr int BM = 64;
    constexpr int MT = 2;
    constexpr int ASTG = BM * SROWH;
    constexpr int BSTG = 128 * SROWH;
    constexpr int STG  = ASTG + BSTG;

    int zsel = blockIdx.z;
    const __half* B = (zsel == 0) ? B0 : (zsel == 1) ? B1 : B2;
    __half*       C = (zsel == 0) ? C0 : (zsel == 1) ? C1 : C2;

    int tid = threadIdx.x;
    int warp = tid >> 5, lane = tid & 31;
    int gid = lane >> 2, tig = lane & 3;
    int g8 = lane >> 3, r8 = lane & 7;
    int wm = warp >> 2, wn = warp & 3;
    int m0 = blockIdx.y * BM, n0 = blockIdx.x * 128;

    // rms scale per row from 8 deterministic partials
    if (tid < 64) {
        float s = 0.f;
        #pragma unroll
        for (int p = 0; p < 8; p++) s += part[p * S_TOK + m0 + tid];
        rs[tid] = rsqrtf(s * (1.0f / HID) + 1e-5f);
    }

    float acc[MT][4][4];
    #pragma unroll
    for (int i = 0; i < MT; i++)
        #pragma unroll
        for (int j = 0; j < 4; j++)
            #pragma unroll
            for (int l = 0; l < 4; l++) acc[i][j][l] = 0.f;

    const int KT = K >> 6;
    constexpr int NCH = (BM + 128) * 8;

    auto load_stage = [&](int kt, int s) {
        int k0 = kt << 6;
        __half* As = tiles + s * STG;
        __half* Bs = As + ASTG;
        #pragma unroll
        for (int i = tid; i < NCH; i += 256) {
            int r = i >> 3, c = (i & 7) << 3;
            if (r < BM) cp16(&As[r * SROWH + c], &A[(size_t)(m0 + r) * K + k0 + c]);
            else {
                int rb = r - BM;
                cp16(&Bs[rb * SROWH + c], &B[(size_t)(n0 + rb) * K + k0 + c]);
            }
        }
        CP_COMMIT();
    };

    uint32_t a_off[MT], b_off[2];
    #pragma unroll
    for (int i = 0; i < MT; i++)
        a_off[i] = (uint32_t)(((wm * 32 + i * 16 + (g8 & 1) * 8 + r8) * SROWH) * 2
                              + (g8 >> 1) * 16);
    #pragma unroll
    for (int jj = 0; jj < 2; jj++)
        b_off[jj] = (uint32_t)(ASTG * 2 + ((wn * 32 + jj * 16 + (g8 >> 1) * 8 + r8) * SROWH) * 2
                               + (g8 & 1) * 16);

    load_stage(0, 0);
    load_stage(1, 1);

    for (int kt = 0; kt < KT; kt++) {
        int s = kt % 3;
        if (kt + 1 < KT) CP_WAIT1(); else CP_WAIT0();
        __syncthreads();
        if (kt + 2 < KT) load_stage(kt + 2, (kt + 2) % 3);
        uint32_t base = smem_u32(tiles + s * STG);
        #pragma unroll
        for (int ks = 0; ks < 4; ks++) {
            uint32_t kofs = base + ks * 32;
            uint32_t af[MT][4];
            #pragma unroll
            for (int i = 0; i < MT; i++)
                ldm_x4(af[i][0], af[i][1], af[i][2], af[i][3], kofs + a_off[i]);
            uint32_t bf[4][2];
            #pragma unroll
            for (int jj = 0; jj < 2; jj++) {
                uint32_t m0r, m1r, m2r, m3r;
                ldm_x4(m0r, m1r, m2r, m3r, kofs + b_off[jj]);
                bf[2 * jj + 0][0] = m0r; bf[2 * jj + 0][1] = m1r;
                bf[2 * jj + 1][0] = m2r; bf[2 * jj + 1][1] = m3r;
            }
            #pragma unroll
            for (int i = 0; i < MT; i++)
                #pragma unroll
                for (int j = 0; j < 4; j++)
                    mma_f16(acc[i][j], af[i], bf[j][0], bf[j][1]);
        }
    }

    if (zsel < 2) {
        __syncthreads();
        __half* Cs = tiles;
        #pragma unroll
        for (int i = 0; i < MT; i++)
            #pragma unroll
            for (int j = 0; j < 4; j++) {
                int rr = wm * 32 + i * 16 + gid;
                int cc = wn * 32 + j * 8 + 2 * tig;
                #pragma unroll
                for (int hh = 0; hh < 2; hh++) {
                    float rv = rs[rr + hh * 8];
                    *(__half2*)&Cs[(rr + hh * 8) * CSR + cc] =
                        __floats2half2_rn(acc[i][j][hh * 2] * rv,
                                          acc[i][j][hh * 2 + 1] * rv);
                }
            }
        __syncthreads();

        float qscale = (zsel == 0) ? 0.125f : 1.0f;
        #pragma unroll
        for (int it = tid; it < 512; it += 256) {
            int r   = it >> 3;
            int sub = it & 7;
            int hh  = sub >> 2;
            int d0  = (sub & 3) * 8;
            int token = m0 + r;
            __half lo[8], hi[8];
            #pragma unroll
            for (int e = 0; e < 8; e++) {
                int d = d0 + e;
                float c  = g_cos[token * HD + d];
                float sn = g_sin[token * HD + d];
                float v0 = __half2float(Cs[r * CSR + hh * 64 + d]);
                float v1 = __half2float(Cs[r * CSR + hh * 64 + d + 32]);
                lo[e] = __float2half((v0 * c - v1 * sn) * qscale);
                hi[e] = __float2half((v1 * c + v0 * sn) * qscale);
            }
            size_t gb = (size_t)token * HID + n0 + hh * 64 + d0;
            *(uint4*)&C[gb]      = *(uint4*)lo;
            *(uint4*)&C[gb + 32] = *(uint4*)hi;
        }
    } else {
        #pragma unroll
        for (int i = 0; i < MT; i++)
            #pragma unroll
            for (int j = 0; j < 4; j++) {
                int rr = wm * 32 + i * 16 + gid;
                int m = m0 + rr;
                int n = n0 + wn * 32 + j * 8 + 2 * tig;
                #pragma unroll
                for (int hh = 0; hh < 2; hh++) {
                    float rv = rs[rr + hh * 8];
                    size_t off = (size_t)(m + hh * 8) * HID + n;
                    *(__half2*)&C[off] =
                        __floats2half2_rn(acc[i][j][hh * 2] * rv,
                                          acc[i][j][hh * 2 + 1] * rv);
                }
            }
    }
}

// ---------------- fused gate||up GEMM (64x128x32), rms-scale + SiLU -------------
__global__ void __launch_bounds__(256) gemm_gateup(
    const __half* __restrict__ A, const __half* __restrict__ G,
    const __half* __restrict__ U, __half* __restrict__ C,
    const float* __restrict__ part, int N, int K)
{
    extern __shared__ __half tiles[];
    __shared__ float rs[64];
    constexpr int BM = 64;
    constexpr int ASTG = BM * SROW2;
    constexpr int BSTG = 128 * SROW2;
    constexpr int STG  = ASTG + 2 * BSTG;

    int tid = threadIdx.x;
    int warp = tid >> 5, lane = tid & 31;
    int gid = lane >> 2, tig = lane & 3;
    int g8 = lane >> 3, r8 = lane & 7;
    int wm = warp >> 2, wn = warp & 3;
    int m0 = blockIdx.y * BM, n0 = blockIdx.x * 128;

    if (tid < 64) {
        float s = 0.f;
        #pragma unroll
        for (int p = 0; p < 8; p++) s += part[p * S_TOK + m0 + tid];
        rs[tid] = rsqrtf(s * (1.0f / HID) + 1e-5f);
    }

    float accg[2][4][4], accu[2][4][4];
    #pragma unroll
    for (int i = 0; i < 2; i++)
        #pragma unroll
        for (int j = 0; j < 4; j++)
            #pragma unroll
            for (int l = 0; l < 4; l++) { accg[i][j][l] = 0.f; accu[i][j][l] = 0.f; }

    const int KT = K >> 5;
    constexpr int NCH = (BM + 256) * 4;

    auto load_stage = [&](int kt, int s) {
        int k0 = kt << 5;
        __half* As = tiles + s * STG;
        __half* Gs = As + ASTG;
        __half* Us = Gs + BSTG;
        #pragma unroll
        for (int i = tid; i < NCH; i += 256) {
            int r = i >> 2, c = (i & 3) << 3;
            if (r < BM) cp16(&As[r * SROW2 + c], &A[(size_t)(m0 + r) * K + k0 + c]);
            else if (r < BM + 128) {
                int rb = r - BM;
                cp16(&Gs[rb * SROW2 + c], &G[(size_t)(n0 + rb) * K + k0 + c]);
            } else {
                int rb = r - BM - 128;
                cp16(&Us[rb * SROW2 + c], &U[(size_t)(n0 + rb) * K + k0 + c]);
            }
        }
        CP_COMMIT();
    };

    uint32_t a_off[2], g_off[2], u_off[2];
    #pragma unroll
    for (int i = 0; i < 2; i++)
        a_off[i] = (uint32_t)(((wm * 32 + i * 16 + (g8 & 1) * 8 + r8) * SROW2) * 2
                              + (g8 >> 1) * 16);
    #pragma unroll
    for (int jj = 0; jj < 2; jj++) {
        uint32_t row = (uint32_t)(wn * 32 + jj * 16 + (g8 >> 1) * 8 + r8);
        g_off[jj] = (uint32_t)(ASTG * 2 + (row * SROW2) * 2 + (g8 & 1) * 16);
        u_off[jj] = g_off[jj] + BSTG * 2;
    }

    load_stage(0, 0);
    load_stage(1, 1);

    for (int kt = 0; kt < KT; kt++) {
        int s = kt % 3;
        if (kt + 1 < KT) CP_WAIT1(); else CP_WAIT0();
        __syncthreads();
        if (kt + 2 < KT) load_stage(kt + 2, (kt + 2) % 3);
        uint32_t base = smem_u32(tiles + s * STG);
        #pragma unroll
        for (int ks = 0; ks < 2; ks++) {
            uint32_t kofs = base + ks * 32;
            uint32_t af[2][4];
            #pragma unroll
            for (int i = 0; i < 2; i++)
                ldm_x4(af[i][0], af[i][1], af[i][2], af[i][3], kofs + a_off[i]);
            uint32_t gf[4][2], uf[4][2];
            #pragma unroll
            for (int jj = 0; jj < 2; jj++) {
                uint32_t m0r, m1r, m2r, m3r;
                ldm_x4(m0r, m1r, m2r, m3r, kofs + g_off[jj]);
                gf[2 * jj + 0][0] = m0r; gf[2 * jj + 0][1] = m1r;
                gf[2 * jj + 1][0] = m2r; gf[2 * jj + 1][1] = m3r;
                ldm_x4(m0r, m1r, m2r, m3r, kofs + u_off[jj]);
                uf[2 * jj + 0][0] = m0r; uf[2 * jj + 0][1] = m1r;
                uf[2 * jj + 1][0] = m2r; uf[2 * jj + 1][1] = m3r;
            }
            #pragma unroll
            for (int i = 0; i < 2; i++)
                #pragma unroll
                for (int j = 0; j < 4; j++) {
                    mma_f16(accg[i][j], af[i], gf[j][0], gf[j][1]);
                    mma_f16(accu[i][j], af[i], uf[j][0], uf[j][1]);
                }
        }
    }

    #pragma unroll
    for (int i = 0; i < 2; i++) {
        #pragma unroll
        for (int j = 0; j < 4; j++) {
            int rr = wm * 32 + i * 16 + gid;
            int m = m0 + rr;
            int n = n0 + wn * 32 + j * 8 + 2 * tig;
            #pragma unroll
            for (int hh = 0; hh < 2; hh++) {
                float rv = rs[rr + hh * 8];
                int mm = m + hh * 8;
                float gg0 = accg[i][j][hh * 2 + 0] * rv, gg1 = accg[i][j][hh * 2 + 1] * rv;
                float v0 = accu[i][j][hh * 2 + 0] * rv * gg0 / (1.0f + __expf(-gg0));
                float v1 = accu[i][j][hh * 2 + 1] * rv * gg1 / (1.0f + __expf(-gg1));
                size_t off = (size_t)mm * N + n;
                *(__half2*)&C[off] = __floats2half2_rn(v0, v1);
            }
        }
    }
}

// ---------------- fp16 flash attention (double-buffered K/V) ---------------------
#define SP 68

__global__ void __launch_bounds__(256) attn_mma_kernel(
    const __half* __restrict__ q, const __half* __restrict__ k,
    const __half* __restrict__ v, __half* __restrict__ o)
{
    extern __shared__ char smraw[];
    __half* Qs = (__half*)smraw;
    __half* Kb = Qs + 64 * SROWH;
    __half* Vb = Kb + 2 * 64 * SROWH;
    __half* Ps = Vb + 2 * 64 * SROWH;
    float*  Ss = (float*)(Ps + 64 * SROWH);
    float*  Al = Ss + 64 * SP;
    float*  Ll = Al + 64;

    int qt = blockIdx.x, h = blockIdx.y;
    int s0 = qt * 64;
    int key0 = (s0 < S0) ? 0 : S0;
    int nkt  = (s0 < S0) ? 16 : 8;

    int tid = threadIdx.x;
    int warp = tid >> 5, lane = tid & 31;
    int gid = lane >> 2, tig = lane & 3;
    int g8 = lane >> 3, r8 = lane & 7;
    int wm = warp >> 1, wn = warp & 1;
    int qq = tid >> 2, kg = tid & 3;

    auto load_tile = [&](int kt) {
        __half* Kd = Kb + (kt & 1) * 64 * SROWH;
        __half* Vd = Vb + (kt & 1) * 64 * SROWH;
        for (int i = tid; i < 1024; i += 256) {
            int sel = i >> 9;
            int i2 = i & 511;
            int r = i2 >> 3, c = (i2 & 7) << 3;
            size_t g = (size_t)(key0 + kt * 64 + r) * HID + h * HD + c;
            if (sel == 0) cp16(&Kd[r * SROWH + c], &k[g]);
            else          cp16(&Vd[r * SROWH + c], &v[g]);
        }
        CP_COMMIT();
    };

    for (int i = tid; i < 512; i += 256) {
        int r = i >> 3, c = (i & 7) << 3;
        cp16(&Qs[r * SROWH + c], &q[(size_t)(s0 + r) * HID + h * HD + c]);
    }
    CP_COMMIT();
    load_tile(0);

    float m_prev = -1e30f, lsum = 0.f;
    float oacc[4][4];
    #pragma unroll
    for (int j = 0; j < 4; j++)
        #pragma unroll
        for (int l = 0; l < 4; l++) oacc[j][l] = 0.f;

    int arow0 = wm * 16 + gid;

    uint32_t qa_off = (uint32_t)(((wm * 16 + (g8 & 1) * 8 + r8) * SROWH) * 2 + (g8 >> 1) * 16);
    uint32_t kb_off[2];
    #pragma unroll
    for (int jj = 0; jj < 2; jj++)
        kb_off[jj] = (uint32_t)(((wn * 32 + jj * 16 + (g8 >> 1) * 8 + r8) * SROWH) * 2
                                + (g8 & 1) * 16);

    uint32_t qbase = smem_u32(Qs);
    uint32_t pbase = smem_u32(Ps);

    for (int kt = 0; kt < nkt; kt++) {
        CP_WAIT0();
        __syncthreads();
        if (kt + 1 < nkt) load_tile(kt + 1);

        uint32_t kbase = smem_u32(Kb + (kt & 1) * 64 * SROWH);
        uint32_t vbase = smem_u32(Vb + (kt & 1) * 64 * SROWH);

        float sc[4][4];
        #pragma unroll
        for (int j = 0; j < 4; j++)
            #pragma unroll
            for (int l = 0; l < 4; l++) sc[j][l] = 0.f;
        #pragma unroll
        for (int ks = 0; ks < 4; ks++) {
            uint32_t kofs = ks * 32;
            uint32_t aq[4];
            ldm_x4(aq[0], aq[1], aq[2], aq[3], qbase + kofs + qa_off);
            uint32_t bf[4][2];
            #pragma unroll
            for (int jj = 0; jj < 2; jj++) {
                uint32_t m0r, m1r, m2r, m3r;
                ldm_x4(m0r, m1r, m2r, m3r, kbase + kofs + kb_off[jj]);
                bf[2 * jj + 0][0] = m0r; bf[2 * jj + 0][1] = m1r;
                bf[2 * jj + 1][0] = m2r; bf[2 * jj + 1][1] = m3r;
            }
            #pragma unroll
            for (int j = 0; j < 4; j++)
                mma_f16(sc[j], aq, bf[j][0], bf[j][1]);
        }
        #pragma unroll
        for (int j = 0; j < 4; j++) {
            int cn = wn * 32 + j * 8 + 2 * tig;
            Ss[arow0 * SP + cn]           = sc[j][0];
            Ss[arow0 * SP + cn + 1]       = sc[j][1];
            Ss[(arow0 + 8) * SP + cn]     = sc[j][2];
            Ss[(arow0 + 8) * SP + cn + 1] = sc[j][3];
        }
        __syncthreads();

        {
            float e[16];
            int base = qq * SP + kg * 16;
            float mloc = -1e30f;
            #pragma unroll
            for (int i = 0; i < 16; i++) { e[i] = Ss[base + i]; mloc = fmaxf(mloc, e[i]); }
            mloc = fmaxf(mloc, __shfl_xor_sync(0xffffffffu, mloc, 1));
            mloc = fmaxf(mloc, __shfl_xor_sync(0xffffffffu, mloc, 2));
            float m_new = fmaxf(m_prev, mloc);
            float alpha = __expf(m_prev - m_new);
            float lrow = 0.f;
            int pb = qq * SROWH + kg * 16;
            #pragma unroll
            for (int i = 0; i < 16; i += 2) {
                float e0 = __expf(e[i]     - m_new);
                float e1 = __expf(e[i + 1] - m_new);
                lrow += e0 + e1;
                *(__half2*)&Ps[pb + i] = __floats2half2_rn(e0, e1);
            }
            lrow += __shfl_xor_sync(0xffffffffu, lrow, 1);
            lrow += __shfl_xor_sync(0xffffffffu, lrow, 2);
            lsum = lsum * alpha + lrow;
            m_prev = m_new;
            if (kg == 0) Al[qq] = alpha;
        }
        __syncthreads();

        float a_r0 = Al[arow0], a_r1 = Al[arow0 + 8];
        #pragma unroll
        for (int j = 0; j < 4; j++) {
            oacc[j][0] *= a_r0; oacc[j][1] *= a_r0;
            oacc[j][2] *= a_r1; oacc[j][3] *= a_r1;
        }

        #pragma unroll
        for (int ks = 0; ks < 4; ks++) {
            uint32_t ap[4];
            ldm_x4(ap[0], ap[1], ap[2], ap[3], pbase + ks * 32 + qa_off);
            uint32_t vf[4][2];
            #pragma unroll
            for (int jj = 0; jj < 2; jj++) {
                uint32_t addr = vbase
                    + (uint32_t)(((ks * 16 + (g8 & 1) * 8 + r8) * SROWH) * 2
                                 + (wn * 32 + jj * 16) * 2 + (g8 >> 1) * 16);
                uint32_t m0r, m1r, m2r, m3r;
                ldm_x4t(m0r, m1r, m2r, m3r, addr);
                vf[2 * jj + 0][0] = m0r; vf[2 * jj + 0][1] = m1r;
                vf[2 * jj + 1][0] = m2r; vf[2 * jj + 1][1] = m3r;
            }
            #pragma unroll
            for (int j = 0; j < 4; j++)
                mma_f16(oacc[j], ap, vf[j][0], vf[j][1]);
        }
        __syncthreads();
    }

    if (kg == 0) Ll[qq] = lsum;
    __syncthreads();
    float inv0 = 1.0f / Ll[arow0];
    float inv1 = 1.0f / Ll[arow0 + 8];
    #pragma unroll
    for (int j = 0; j < 4; j++) {
        int cn = wn * 32 + j * 8 + 2 * tig;
        size_t o0 = (size_t)(s0 + arow0) * HID + h * HD + cn;
        size_t o1 = (size_t)(s0 + arow0 + 8) * HID + h * HD + cn;
        *(__half2*)&o[o0] = __floats2half2_rn(oacc[j][0] * inv0, oacc[j][1] * inv0);
        *(__half2*)&o[o1] = __floats2half2_rn(oacc[j][2] * inv1, oacc[j][3] * inv1);
    }
}

// ---------------- host orchestration ---------------------------------------------
extern "C" void kernel_launch(void* const* d_in, const int* in_sizes, int n_in,
                              void* d_out, int out_size) {
    const float* img0        = (const float*)d_in[0];
    const float* img1        = (const float*)d_in[1];
    const float* conv_w      = (const float*)d_in[2];
    const float* ln_pre_w    = (const float*)d_in[3];
    const float* attn_norm_w = (const float*)d_in[4];
    const float* q_w         = (const float*)d_in[5];
    const float* k_w         = (const float*)d_in[6];
    const float* v_w         = (const float*)d_in[7];
    const float* o_w         = (const float*)d_in[8];
    const float* ffn_norm_w  = (const float*)d_in[9];
    const float* gate_w      = (const float*)d_in[10];
    const float* up_w        = (const float*)d_in[11];
    const float* down_w      = (const float*)d_in[12];
    float* out = (float*)d_out;

    float *p_x, *p_h2, *p_pa, *p_pf;
    __half *p_xpatch, *p_ax, *p_ax2, *p_q, *p_k, *p_v, *p_ao, *p_t;
    __half *p_wconv, *p_wq, *p_wk, *p_wv, *p_wo, *p_wg, *p_wu, *p_wd;
    cudaGetSymbolAddress((void**)&p_x,  g_x);
    cudaGetSymbolAddress((void**)&p_h2, g_h2);
    cudaGetSymbolAddress((void**)&p_pa, g_pa);
    cudaGetSymbolAddress((void**)&p_pf, g_pf);
    cudaGetSymbolAddress((void**)&p_xpatch, a_xpatch);
    cudaGetSymbolAddress((void**)&p_ax,  a_x);
    cudaGetSymbolAddress((void**)&p_ax2, a_x2);
    cudaGetSymbolAddress((void**)&p_q,  a_q);
    cudaGetSymbolAddress((void**)&p_k,  a_k);
    cudaGetSymbolAddress((void**)&p_v,  a_v);
    cudaGetSymbolAddress((void**)&p_ao, a_ao);
    cudaGetSymbolAddress((void**)&p_t,  a_t);
    cudaGetSymbolAddress((void**)&p_wconv, h_wconv);
    cudaGetSymbolAddress((void**)&p_wq, h_wq);
    cudaGetSymbolAddress((void**)&p_wk, h_wk);
    cudaGetSymbolAddress((void**)&p_wv, h_wv);
    cudaGetSymbolAddress((void**)&p_wo, h_wo);
    cudaGetSymbolAddress((void**)&p_wg, h_wg);
    cudaGetSymbolAddress((void**)&p_wu, h_wu);
    cudaGetSymbolAddress((void**)&p_wd, h_wd);

    const int SMEM64  = 3 * (64 + 128) * SROWH * 2;   // 82944
    const int SMEMGU  = 3 * (64 + 256) * SROW2 * 2;   // 76800
    const int ASMEM   = 6 * 64 * SROWH * 2 + 64 * SP * 4 + 2 * 64 * 4;
    cudaFuncSetAttribute((const void*)gemm_f16<0, false, 0>, cudaFuncAttributeMaxDynamicSharedMemorySize, SMEM64);
    cudaFuncSetAttribute((const void*)gemm_f16<1, false, 0>, cudaFuncAttributeMaxDynamicSharedMemorySize, SMEM64);
    cudaFuncSetAttribute((const void*)gemm_f16<1, false, 1>, cudaFuncAttributeMaxDynamicSharedMemorySize, SMEM64);
    cudaFuncSetAttribute((const void*)gemm_qkv,              cudaFuncAttributeMaxDynamicSharedMemorySize, SMEM64);
    cudaFuncSetAttribute((const void*)gemm_gateup,           cudaFuncAttributeMaxDynamicSharedMemorySize, SMEMGU);
    cudaFuncSetAttribute((const void*)attn_mma_kernel,       cudaFuncAttributeMaxDynamicSharedMemorySize, ASMEM);

    // ---- side stream: weight conversion (norm weights folded) ----
    cudaStream_t s2;
    cudaStreamCreateWithFlags(&s2, cudaStreamNonBlocking);
    cudaEvent_t evFork, evConv, evL[NLAYERS];
    cudaEventCreateWithFlags(&evFork, cudaEventDisableTiming);
    cudaEventCreateWithFlags(&evConv, cudaEventDisableTiming);
    for (int l = 0; l < NLAYERS; l++) cudaEventCreateWithFlags(&evL[l], cudaEventDisableTiming);

    cudaEventRecord(evFork, 0);
    cudaStreamWaitEvent(s2, evFork, 0);

    auto cvt = [&](const float* src, __half* dst, int n) {
        f2h_kernel<<<(n / 16 + 255) / 256, 256, 0, s2>>>(src, dst, n / 16);
    };
    auto cvtn = [&](const float* src, const float* nw, __half* dst, int n) {
        f2h_norm_kernel<<<(n / 16 + 255) / 256, 256, 0, s2>>>(src, nw, dst, n / 16);
    };
    cvt(conv_w, p_wconv, HID * KPATCH);
    cudaEventRecord(evConv, s2);
    for (int l = 0; l < NLAYERS; l++) {
        const float* anw = attn_norm_w + l * HID;
        const float* fnw = ffn_norm_w  + l * HID;
        cvtn(q_w    + (size_t)l * HID * HID,   anw, p_wq + (size_t)l * HID * HID,   HID * HID);
        cvtn(k_w    + (size_t)l * HID * HID,   anw, p_wk + (size_t)l * HID * HID,   HID * HID);
        cvtn(v_w    + (size_t)l * HID * HID,   anw, p_wv + (size_t)l * HID * HID,   HID * HID);
        cvt (o_w    + (size_t)l * HID * HID,        p_wo + (size_t)l * HID * HID,   HID * HID);
        cvtn(gate_w + (size_t)l * INTER * HID, fnw, p_wg + (size_t)l * INTER * HID, INTER * HID);
        cvtn(up_w   + (size_t)l * INTER * HID, fnw, p_wu + (size_t)l * INTER * HID, INTER * HID);
        cvt (down_w + (size_t)l * HID * INTER,      p_wd + (size_t)l * HID * INTER, HID * INTER);
        cudaEventRecord(evL[l], s2);
    }

    dim3 grid_n1k(HID / 128, S_TOK / 64);       // (8, 24)
    dim3 grid_qkv(HID / 128, S_TOK / 64, 3);    // (8, 24, 3)
    dim3 grid_gu (INTER / 128, S_TOK / 64);     // (32, 24)

    im2col_kernel<<<(S_TOK * KPATCH + 255) / 256, 256>>>(img0, img1);
    rope_table_kernel<<<S_TOK, 64>>>();
    cudaStreamWaitEvent(0, evConv, 0);
    gemm_f16<0, false, 0><<<grid_n1k, 256, SMEM64>>>(
        p_xpatch, p_wconv, nullptr, p_h2, nullptr, nullptr, HID, KPATCH);

    // ln_pre: x fp32 + half copy + attn-rms sumsq partials (slot 0 + zeros)
    lnpre_kernel<<<S_TOK, 256>>>(p_h2, ln_pre_w, p_x, p_ax, p_pa);

    for (int l = 0; l < NLAYERS; l++) {
        const __half* qw = p_wq + (size_t)l * HID * HID;
        const __half* kw = p_wk + (size_t)l * HID * HID;
        const __half* vw = p_wv + (size_t)l * HID * HID;
        const __half* ow = p_wo + (size_t)l * HID * HID;
        const __half* gw = p_wg + (size_t)l * INTER * HID;
        const __half* uw = p_wu + (size_t)l * INTER * HID;
        const __half* dw = p_wd + (size_t)l * HID * INTER;

        cudaStreamWaitEvent(0, evL[l], 0);   // layer-l weights ready

        // QKV with rms-scale (from g_pa) + fused RoPE
        gemm_qkv<<<grid_qkv, 256, SMEM64>>>(p_ax, qw, kw, vw, p_q, p_k, p_v, p_pa, HID);

        attn_mma_kernel<<<dim3(S_TOK / 64, HEADS), 256, ASMEM>>>(p_q, p_k, p_v, p_ao);

        // o-proj: h2 = x + ao@ow ; emit half h2 + ffn-rms partials
        gemm_f16<1, false, 1><<<grid_n1k, 256, SMEM64>>>(
            p_ao, ow, p_x, p_h2, p_ax2, p_pf, HID, HID);

        // gate||up with rms-scale (from g_pf) + SiLU
        gemm_gateup<<<grid_gu, 256, SMEMGU>>>(p_ax2, gw, uw, p_t, p_pf, INTER, HID);

        // down-proj: next x = h2 + t@dw ; emit half x + attn-rms partials
        if (l < NLAYERS - 1) {
            gemm_f16<1, false, 1><<<grid_n1k, 256, SMEM64>>>(
                p_t, dw, p_h2, p_x, p_ax, p_pa, HID, INTER);
        } else {
            gemm_f16<1, false, 0><<<grid_n1k, 256, SMEM64>>>(
                p_t, dw, p_h2, out, nullptr, nullptr, HID, INTER);
        }
    }
    // streams/events intentionally not destroyed (active graph capture).
}

// round 16
// speedup vs baseline: 1.0329x; 1.0054x over previous
#include <cuda_runtime.h>
#include <cuda_fp16.h>
#include <math.h>
#include <stdint.h>

// ---------------- problem constants ----------------------------------------
#define S_TOK 1536
#define S0    1024
#define HID   1024
#define HEADS 16
#define HD    64
#define INTER 4096
#define NLAYERS 4
#define KPATCH 768

// ---------------- scratch ---------------------------------------------------
__device__ float g_x [S_TOK * HID];
__device__ float g_h2[S_TOK * HID];
__device__ float g_cos[S_TOK * HD];
__device__ float g_sin[S_TOK * HD];
__device__ float g_pa[8 * S_TOK];   // partial sumsq for attn-rms (per n-block)
__device__ float g_pf[8 * S_TOK];   // partial sumsq for ffn-rms
__device__ __half a_xpatch[S_TOK * KPATCH];
__device__ __half a_x [S_TOK * HID];    // half copy of x  (attn-rms input)
__device__ __half a_x2[S_TOK * HID];    // half copy of h2 (ffn-rms input)
__device__ __half a_q [S_TOK * HID];
__device__ __half a_k [S_TOK * HID];
__device__ __half a_v [S_TOK * HID];
__device__ __half a_ao[S_TOK * HID];
__device__ __half a_t [S_TOK * INTER];
__device__ __half h_wconv[HID * KPATCH];
__device__ __half h_wq[NLAYERS * HID * HID];
__device__ __half h_wk[NLAYERS * HID * HID];
__device__ __half h_wv[NLAYERS * HID * HID];
__device__ __half h_wo[NLAYERS * HID * HID];
__device__ __half h_wg[NLAYERS * INTER * HID];
__device__ __half h_wu[NLAYERS * INTER * HID];
__device__ __half h_wd[NLAYERS * HID * INTER];

// ---------------- helpers ----------------------------------------------------
__device__ __forceinline__ uint32_t smem_u32(const void* p) {
    return (uint32_t)__cvta_generic_to_shared(p);
}
__device__ __forceinline__ void mma_f16(float c[4], const uint32_t a[4],
                                        uint32_t b0, uint32_t b1) {
    asm volatile(
        "mma.sync.aligned.m16n8k16.row.col.f32.f16.f16.f32 "
        "{%0,%1,%2,%3},{%4,%5,%6,%7},{%8,%9},{%0,%1,%2,%3};"
        : "+f"(c[0]), "+f"(c[1]), "+f"(c[2]), "+f"(c[3])
        : "r"(a[0]), "r"(a[1]), "r"(a[2]), "r"(a[3]), "r"(b0), "r"(b1));
}
__device__ __forceinline__ void ldm_x4(uint32_t& r0, uint32_t& r1, uint32_t& r2, uint32_t& r3,
                                       uint32_t addr) {
    asm volatile("ldmatrix.sync.aligned.m8n8.x4.shared.b16 {%0,%1,%2,%3}, [%4];"
                 : "=r"(r0), "=r"(r1), "=r"(r2), "=r"(r3) : "r"(addr));
}
__device__ __forceinline__ void ldm_x4t(uint32_t& r0, uint32_t& r1, uint32_t& r2, uint32_t& r3,
                                        uint32_t addr) {
    asm volatile("ldmatrix.sync.aligned.m8n8.x4.trans.shared.b16 {%0,%1,%2,%3}, [%4];"
                 : "=r"(r0), "=r"(r1), "=r"(r2), "=r"(r3) : "r"(addr));
}
__device__ __forceinline__ void cp16(void* smem_dst, const void* gsrc) {
    uint32_t d = (uint32_t)__cvta_generic_to_shared(smem_dst);
    asm volatile("cp.async.cg.shared.global [%0], [%1], 16;\n" :: "r"(d), "l"(gsrc));
}
#define CP_COMMIT() asm volatile("cp.async.commit_group;\n" ::: "memory")
#define CP_WAIT0()  asm volatile("cp.async.wait_group 0;\n" ::: "memory")
#define CP_WAIT1()  asm volatile("cp.async.wait_group 1;\n" ::: "memory")

// ---------------- weight fp32 -> fp16 (plain) ----------------------------------
__global__ void f2h_kernel(const float* __restrict__ x, __half* __restrict__ y, int n16) {
    int i = blockIdx.x * blockDim.x + threadIdx.x;
    if (i >= n16) return;
    const float4* x4 = (const float4*)x;
    float4 v0 = x4[4 * i + 0];
    float4 v1 = x4[4 * i + 1];
    float4 v2 = x4[4 * i + 2];
    float4 v3 = x4[4 * i + 3];
    __half2 h0 = __floats2half2_rn(v0.x, v0.y), h1 = __floats2half2_rn(v0.z, v0.w);
    __half2 h2 = __floats2half2_rn(v1.x, v1.y), h3 = __floats2half2_rn(v1.z, v1.w);
    __half2 h4 = __floats2half2_rn(v2.x, v2.y), h5 = __floats2half2_rn(v2.z, v2.w);
    __half2 h6 = __floats2half2_rn(v3.x, v3.y), h7 = __floats2half2_rn(v3.z, v3.w);
    uint4 ua, ub;
    ua.x = *(uint32_t*)&h0; ua.y = *(uint32_t*)&h1;
    ua.z = *(uint32_t*)&h2; ua.w = *(uint32_t*)&h3;
    ub.x = *(uint32_t*)&h4; ub.y = *(uint32_t*)&h5;
    ub.z = *(uint32_t*)&h6; ub.w = *(uint32_t*)&h7;
    ((uint4*)y)[2 * i + 0] = ua;
    ((uint4*)y)[2 * i + 1] = ub;
}

// ---------------- weight fp32 -> fp16 with rms-norm weight folded (K=1024) ------
__global__ void f2h_norm_kernel(const float* __restrict__ x, const float* __restrict__ nw,
                                __half* __restrict__ y, int n16) {
    int i = blockIdx.x * blockDim.x + threadIdx.x;
    if (i >= n16) return;
    int kb = (16 * i) & 1023;
    const float4* x4 = (const float4*)x;
    const float4* w4 = (const float4*)(nw + kb);
    float4 v0 = x4[4 * i + 0], w0 = w4[0];
    float4 v1 = x4[4 * i + 1], w1 = w4[1];
    float4 v2 = x4[4 * i + 2], w2 = w4[2];
    float4 v3 = x4[4 * i + 3], w3 = w4[3];
    __half2 h0 = __floats2half2_rn(v0.x * w0.x, v0.y * w0.y);
    __half2 h1 = __floats2half2_rn(v0.z * w0.z, v0.w * w0.w);
    __half2 h2 = __floats2half2_rn(v1.x * w1.x, v1.y * w1.y);
    __half2 h3 = __floats2half2_rn(v1.z * w1.z, v1.w * w1.w);
    __half2 h4 = __floats2half2_rn(v2.x * w2.x, v2.y * w2.y);
    __half2 h5 = __floats2half2_rn(v2.z * w2.z, v2.w * w2.w);
    __half2 h6 = __floats2half2_rn(v3.x * w3.x, v3.y * w3.y);
    __half2 h7 = __floats2half2_rn(v3.z * w3.z, v3.w * w3.w);
    uint4 ua, ub;
    ua.x = *(uint32_t*)&h0; ua.y = *(uint32_t*)&h1;
    ua.z = *(uint32_t*)&h2; ua.w = *(uint32_t*)&h3;
    ub.x = *(uint32_t*)&h4; ub.y = *(uint32_t*)&h5;
    ub.z = *(uint32_t*)&h6; ub.w = *(uint32_t*)&h7;
    ((uint4*)y)[2 * i + 0] = ua;
    ((uint4*)y)[2 * i + 1] = ub;
}

// ---------------- prep: im2col + rope table in one launch -----------------------
#define IM2COL_BLOCKS 4608   // 1536*768/256
__global__ void __launch_bounds__(256) prep_kernel(
    const float* __restrict__ img0, const float* __restrict__ img1)
{
    if (blockIdx.x < IM2COL_BLOCKS) {
        int idx = blockIdx.x * 256 + threadIdx.x;
        int s = idx / KPATCH;
        int r = idx - s * KPATCH;
        int c  = r >> 8;
        int kh = (r >> 4) & 15;
        int kw = r & 15;
        float val;
        if (s < S0) {
            int ph = s >> 5, pw = s & 31;
            val = img0[c * 512 * 512 + (ph * 16 + kh) * 512 + (pw * 16 + kw)];
        } else {
            int sp = s - S0;
            int ph = sp >> 4, pw = sp & 15;
            val = img1[c * 512 * 256 + (ph * 16 + kh) * 256 + (pw * 16 + kw)];
        }
        a_xpatch[idx] = __float2half(val);
    } else {
        int b = blockIdx.x - IM2COL_BLOCKS;
        int s = b * 4 + (threadIdx.x >> 6);
        int d = threadIdx.x & 63;
        int ph, pw;
        if (s < S0) { ph = s >> 5; pw = s & 31; }
        else        { int sp = s - S0; ph = sp >> 4; pw = sp & 15; }
        int j = d & 31;
        float e, base;
        if (j < 16) { e = (4.0f * j) / 64.0f;               base = (float)ph; }
        else        { e = (2.0f + 4.0f * (j - 16)) / 64.0f; base = (float)pw; }
        float f = base * expf(-e * 9.2103403719761836f);
        g_cos[s * HD + d] = cosf(f);
        g_sin[s * HD + d] = sinf(f);
    }
}

// ---------------- ln_pre: rms + emit half copy + sumsq partials -----------------
__global__ void lnpre_kernel(const float* __restrict__ h2,
                             const float* __restrict__ w,
                             float* __restrict__ x,
                             __half* __restrict__ xh,
                             float* __restrict__ part) {
    int s = blockIdx.x;
    int tid = threadIdx.x;  // 256
    const float* xr = h2 + s * HID;
    float ss = 0.f;
    #pragma unroll 4
    for (int i = tid; i < HID; i += 256) { float v = xr[i]; ss += v * v; }
    __shared__ float sh[8];
    #pragma unroll
    for (int o = 16; o > 0; o >>= 1) ss += __shfl_xor_sync(0xffffffffu, ss, o);
    if ((tid & 31) == 0) sh[tid >> 5] = ss;
    __syncthreads();
    if (tid < 8) {
        float v = sh[tid];
        #pragma unroll
        for (int o = 4; o > 0; o >>= 1) v += __shfl_xor_sync(0xffu, v, o);
        if (tid == 0) sh[0] = v;
    }
    __syncthreads();
    float r = rsqrtf(sh[0] * (1.0f / HID) + 1e-5f);
    __syncthreads();
    float ss2 = 0.f;
    for (int i = tid; i < HID; i += 256) {
        float v = xr[i] * r * w[i];
        x[s * HID + i] = v;
        xh[s * HID + i] = __float2half(v);
        ss2 += v * v;
    }
    #pragma unroll
    for (int o = 16; o > 0; o >>= 1) ss2 += __shfl_xor_sync(0xffffffffu, ss2, o);
    if ((tid & 31) == 0) sh[tid >> 5] = ss2;
    __syncthreads();
    if (tid < 8) {
        float v = sh[tid];
        #pragma unroll
        for (int o = 4; o > 0; o >>= 1) v += __shfl_xor_sync(0xffu, v, o);
        if (tid == 0) part[s] = v;          // slot 0
    }
    if (tid >= 8 && tid < 15) part[(tid - 7) * S_TOK + s] = 0.f;  // slots 1..7
}

#define SROWH 72   // halves per smem row (64 data + 8 pad)
#define SROW2 40   // halves per row for BK=32 (32 data + 8 pad)

// ---------------- fp16 GEMM core (64x128x64, 2m x 4n warps) --------------------
// EPI: 0=plain, 1=+aux(fp32 residual)
// EMIT: 1 -> also write half copy of output (xh) and per-(CTA,row) sumsq partials.
template<int EPI, bool OUT_HALF, int EMIT>
__device__ __forceinline__ void gemm_body(
    const __half* __restrict__ A, const __half* __restrict__ B,
    const void* __restrict__ auxp, void* __restrict__ Cp,
    __half* __restrict__ xh, float* __restrict__ part,
    int N, int K, __half* tiles)
{
    constexpr int BM = 64;
    constexpr int MT = 2;
    constexpr int ASTG = BM * SROWH;
    constexpr int BSTG = 128 * SROWH;
    constexpr int STG  = ASTG + BSTG;

    int tid = threadIdx.x;
    int warp = tid >> 5, lane = tid & 31;
    int gid = lane >> 2, tig = lane & 3;
    int g8 = lane >> 3, r8 = lane & 7;
    int wm = warp >> 2, wn = warp & 3;
    int m0 = blockIdx.y * BM, n0 = blockIdx.x * 128;

    float acc[MT][4][4];
    #pragma unroll
    for (int i = 0; i < MT; i++)
        #pragma unroll
        for (int j = 0; j < 4; j++)
            #pragma unroll
            for (int l = 0; l < 4; l++) acc[i][j][l] = 0.f;

    const int KT = K >> 6;
    constexpr int NCH = (BM + 128) * 8;

    auto load_stage = [&](int kt, int s) {
        int k0 = kt << 6;
        __half* As = tiles + s * STG;
        __half* Bs = As + ASTG;
        #pragma unroll
        for (int i = tid; i < NCH; i += 256) {
            int r = i >> 3, c = (i & 7) << 3;
            if (r < BM) cp16(&As[r * SROWH + c], &A[(size_t)(m0 + r) * K + k0 + c]);
            else {
                int rb = r - BM;
                cp16(&Bs[rb * SROWH + c], &B[(size_t)(n0 + rb) * K + k0 + c]);
            }
        }
        CP_COMMIT();
    };

    uint32_t a_off[MT], b_off[2];
    #pragma unroll
    for (int i = 0; i < MT; i++)
        a_off[i] = (uint32_t)(((wm * 32 + i * 16 + (g8 & 1) * 8 + r8) * SROWH) * 2
                              + (g8 >> 1) * 16);
    #pragma unroll
    for (int jj = 0; jj < 2; jj++)
        b_off[jj] = (uint32_t)(ASTG * 2 + ((wn * 32 + jj * 16 + (g8 >> 1) * 8 + r8) * SROWH) * 2
                               + (g8 & 1) * 16);

    load_stage(0, 0);
    load_stage(1, 1);

    for (int kt = 0; kt < KT; kt++) {
        int s = kt % 3;
        if (kt + 1 < KT) CP_WAIT1(); else CP_WAIT0();
        __syncthreads();
        if (kt + 2 < KT) load_stage(kt + 2, (kt + 2) % 3);
        uint32_t base = smem_u32(tiles + s * STG);
        #pragma unroll
        for (int ks = 0; ks < 4; ks++) {
            uint32_t kofs = base + ks * 32;
            uint32_t af[MT][4];
            #pragma unroll
            for (int i = 0; i < MT; i++)
                ldm_x4(af[i][0], af[i][1], af[i][2], af[i][3], kofs + a_off[i]);
            uint32_t bf[4][2];
            #pragma unroll
            for (int jj = 0; jj < 2; jj++) {
                uint32_t m0r, m1r, m2r, m3r;
                ldm_x4(m0r, m1r, m2r, m3r, kofs + b_off[jj]);
                bf[2 * jj + 0][0] = m0r; bf[2 * jj + 0][1] = m1r;
                bf[2 * jj + 1][0] = m2r; bf[2 * jj + 1][1] = m3r;
            }
            #pragma unroll
            for (int i = 0; i < MT; i++)
                #pragma unroll
                for (int j = 0; j < 4; j++)
                    mma_f16(acc[i][j], af[i], bf[j][0], bf[j][1]);
        }
    }

    const float* auxf = (const float*)auxp;
    float ssq[2][2] = {{0.f, 0.f}, {0.f, 0.f}};
    #pragma unroll
    for (int i = 0; i < MT; i++) {
        #pragma unroll
        for (int j = 0; j < 4; j++) {
            int m = m0 + wm * 32 + i * 16 + gid;
            int n = n0 + wn * 32 + j * 8 + 2 * tig;
            #pragma unroll
            for (int hh = 0; hh < 2; hh++) {
                int mm = m + hh * 8;
                float v0 = acc[i][j][hh * 2 + 0];
                float v1 = acc[i][j][hh * 2 + 1];
                size_t off = (size_t)mm * N + n;
                if (EPI == 1) { v0 += auxf[off]; v1 += auxf[off + 1]; }
                if (OUT_HALF) {
                    *(__half2*)&((__half*)Cp)[off] = __floats2half2_rn(v0, v1);
                } else {
                    float2 o2; o2.x = v0; o2.y = v1;
                    *(float2*)&((float*)Cp)[off] = o2;
                }
                if (EMIT) {
                    *(__half2*)&xh[off] = __floats2half2_rn(v0, v1);
                    ssq[i][hh] += v0 * v0 + v1 * v1;
                }
            }
        }
    }

    if (EMIT) {
        #pragma unroll
        for (int i = 0; i < 2; i++)
            #pragma unroll
            for (int hh = 0; hh < 2; hh++) {
                ssq[i][hh] += __shfl_xor_sync(0xffffffffu, ssq[i][hh], 1);
                ssq[i][hh] += __shfl_xor_sync(0xffffffffu, ssq[i][hh], 2);
            }
        __syncthreads();
        float* sw = (float*)tiles;
        if (tig == 0) {
            #pragma unroll
            for (int i = 0; i < 2; i++)
                #pragma unroll
                for (int hh = 0; hh < 2; hh++)
                    sw[wn * 64 + wm * 32 + i * 16 + gid + hh * 8] = ssq[i][hh];
        }
        __syncthreads();
        if (tid < 64)
            part[blockIdx.x * S_TOK + m0 + tid] =
                sw[tid] + sw[64 + tid] + sw[128 + tid] + sw[192 + tid];
    }
}

template<int EPI, bool OUT_HALF, int EMIT>
__global__ void __launch_bounds__(256) gemm_f16(
    const __half* __restrict__ A, const __half* __restrict__ B,
    const void* __restrict__ aux, void* __restrict__ C,
    __half* __restrict__ xh, float* __restrict__ part, int N, int K)
{
    extern __shared__ __half tiles[];
    gemm_body<EPI, OUT_HALF, EMIT>(A, B, aux, C, xh, part, N, K, tiles);
}

// ---------------- QKV GEMM: rms-scale epilogue + fused RoPE ---------------------
#define CSR 136

__global__ void __launch_bounds__(256) gemm_qkv(
    const __half* __restrict__ A,
    const __half* __restrict__ B0, const __half* __restrict__ B1, const __half* __restrict__ B2,
    __half* __restrict__ C0, __half* __restrict__ C1, __half* __restrict__ C2,
    const float* __restrict__ part, int K)
{
    extern __shared__ __half tiles[];
    __shared__ float rs[64];
    constexpr int BM = 64;
    constexpr int MT = 2;
    constexpr int ASTG = BM * SROWH;
    constexpr int BSTG = 128 * SROWH;
    constexpr int STG  = ASTG + BSTG;

    int zsel = blockIdx.z;
    const __half* B = (zsel == 0) ? B0 : (zsel == 1) ? B1 : B2;
    __half*       C = (zsel == 0) ? C0 : (zsel == 1) ? C1 : C2;

    int tid = threadIdx.x;
    int warp = tid >> 5, lane = tid & 31;
    int gid = lane >> 2, tig = lane & 3;
    int g8 = lane >> 3, r8 = lane & 7;
    int wm = warp >> 2, wn = warp & 3;
    int m0 = blockIdx.y * BM, n0 = blockIdx.x * 128;

    if (tid < 64) {
        float s = 0.f;
        #pragma unroll
        for (int p = 0; p < 8; p++) s += part[p * S_TOK + m0 + tid];
        rs[tid] = rsqrtf(s * (1.0f / HID) + 1e-5f);
    }

    float acc[MT][4][4];
    #pragma unroll
    for (int i = 0; i < MT; i++)
        #pragma unroll
        for (int j = 0; j < 4; j++)
            #pragma unroll
            for (int l = 0; l < 4; l++) acc[i][j][l] = 0.f;

    const int KT = K >> 6;
    constexpr int NCH = (BM + 128) * 8;

    auto load_stage = [&](int kt, int s) {
        int k0 = kt << 6;
        __half* As = tiles + s * STG;
        __half* Bs = As + ASTG;
        #pragma unroll
        for (int i = tid; i < NCH; i += 256) {
            int r = i >> 3, c = (i & 7) << 3;
            if (r < BM) cp16(&As[r * SROWH + c], &A[(size_t)(m0 + r) * K + k0 + c]);
            else {
                int rb = r - BM;
                cp16(&Bs[rb * SROWH + c], &B[(size_t)(n0 + rb) * K + k0 + c]);
            }
        }
        CP_COMMIT();
    };

    uint32_t a_off[MT], b_off[2];
    #pragma unroll
    for (int i = 0; i < MT; i++)
        a_off[i] = (uint32_t)(((wm * 32 + i * 16 + (g8 & 1) * 8 + r8) * SROWH) * 2
                              + (g8 >> 1) * 16);
    #pragma unroll
    for (int jj = 0; jj < 2; jj++)
        b_off[jj] = (uint32_t)(ASTG * 2 + ((wn * 32 + jj * 16 + (g8 >> 1) * 8 + r8) * SROWH) * 2
                               + (g8 & 1) * 16);

    load_stage(0, 0);
    load_stage(1, 1);

    for (int kt = 0; kt < KT; kt++) {
        int s = kt % 3;
        if (kt + 1 < KT) CP_WAIT1(); else CP_WAIT0();
        __syncthreads();
        if (kt + 2 < KT) load_stage(kt + 2, (kt + 2) % 3);
        uint32_t base = smem_u32(tiles + s * STG);
        #pragma unroll
        for (int ks = 0; ks < 4; ks++) {
            uint32_t kofs = base + ks * 32;
            uint32_t af[MT][4];
            #pragma unroll
            for (int i = 0; i < MT; i++)
                ldm_x4(af[i][0], af[i][1], af[i][2], af[i][3], kofs + a_off[i]);
            uint32_t bf[4][2];
            #pragma unroll
            for (int jj = 0; jj < 2; jj++) {
                uint32_t m0r, m1r, m2r, m3r;
                ldm_x4(m0r, m1r, m2r, m3r, kofs + b_off[jj]);
                bf[2 * jj + 0][0] = m0r; bf[2 * jj + 0][1] = m1r;
                bf[2 * jj + 1][0] = m2r; bf[2 * jj + 1][1] = m3r;
            }
            #pragma unroll
            for (int i = 0; i < MT; i++)
                #pragma unroll
                for (int j = 0; j < 4; j++)
                    mma_f16(acc[i][j], af[i], bf[j][0], bf[j][1]);
        }
    }

    if (zsel < 2) {
        __syncthreads();
        __half* Cs = tiles;
        #pragma unroll
        for (int i = 0; i < MT; i++)
            #pragma unroll
            for (int j = 0; j < 4; j++) {
                int rr = wm * 32 + i * 16 + gid;
                int cc = wn * 32 + j * 8 + 2 * tig;
                #pragma unroll
                for (int hh = 0; hh < 2; hh++) {
                    float rv = rs[rr + hh * 8];
                    *(__half2*)&Cs[(rr + hh * 8) * CSR + cc] =
                        __floats2half2_rn(acc[i][j][hh * 2] * rv,
                                          acc[i][j][hh * 2 + 1] * rv);
                }
            }
        __syncthreads();

        float qscale = (zsel == 0) ? 0.125f : 1.0f;
        #pragma unroll
        for (int it = tid; it < 512; it += 256) {
            int r   = it >> 3;
            int sub = it & 7;
            int hh  = sub >> 2;
            int d0  = (sub & 3) * 8;
            int token = m0 + r;
            __half lo[8], hi[8];
            #pragma unroll
            for (int e = 0; e < 8; e++) {
                int d = d0 + e;
                float c  = g_cos[token * HD + d];
                float sn = g_sin[token * HD + d];
                float v0 = __half2float(Cs[r * CSR + hh * 64 + d]);
                float v1 = __half2float(Cs[r * CSR + hh * 64 + d + 32]);
                lo[e] = __float2half((v0 * c - v1 * sn) * qscale);
                hi[e] = __float2half((v1 * c + v0 * sn) * qscale);
            }
            size_t gb = (size_t)token * HID + n0 + hh * 64 + d0;
            *(uint4*)&C[gb]      = *(uint4*)lo;
            *(uint4*)&C[gb + 32] = *(uint4*)hi;
        }
    } else {
        #pragma unroll
        for (int i = 0; i < MT; i++)
            #pragma unroll
            for (int j = 0; j < 4; j++) {
                int rr = wm * 32 + i * 16 + gid;
                int m = m0 + rr;
                int n = n0 + wn * 32 + j * 8 + 2 * tig;
                #pragma unroll
                for (int hh = 0; hh < 2; hh++) {
                    float rv = rs[rr + hh * 8];
                    size_t off = (size_t)(m + hh * 8) * HID + n;
                    *(__half2*)&C[off] =
                        __floats2half2_rn(acc[i][j][hh * 2] * rv,
                                          acc[i][j][hh * 2 + 1] * rv);
                }
            }
    }
}

// ---------------- fused gate||up GEMM (64x128x32), rms-scale + SiLU -------------
__global__ void __launch_bounds__(256) gemm_gateup(
    const __half* __restrict__ A, const __half* __restrict__ G,
    const __half* __restrict__ U, __half* __restrict__ C,
    const float* __restrict__ part, int N, int K)
{
    extern __shared__ __half tiles[];
    __shared__ float rs[64];
    constexpr int BM = 64;
    constexpr int ASTG = BM * SROW2;
    constexpr int BSTG = 128 * SROW2;
    constexpr int STG  = ASTG + 2 * BSTG;

    int tid = threadIdx.x;
    int warp = tid >> 5, lane = tid & 31;
    int gid = lane >> 2, tig = lane & 3;
    int g8 = lane >> 3, r8 = lane & 7;
    int wm = warp >> 2, wn = warp & 3;
    int m0 = blockIdx.y * BM, n0 = blockIdx.x * 128;

    if (tid < 64) {
        float s = 0.f;
        #pragma unroll
        for (int p = 0; p < 8; p++) s += part[p * S_TOK + m0 + tid];
        rs[tid] = rsqrtf(s * (1.0f / HID) + 1e-5f);
    }

    float accg[2][4][4], accu[2][4][4];
    #pragma unroll
    for (int i = 0; i < 2; i++)
        #pragma unroll
        for (int j = 0; j < 4; j++)
            #pragma unroll
            for (int l = 0; l < 4; l++) { accg[i][j][l] = 0.f; accu[i][j][l] = 0.f; }

    const int KT = K >> 5;
    constexpr int NCH = (BM + 256) * 4;

    auto load_stage = [&](int kt, int s) {
        int k0 = kt << 5;
        __half* As = tiles + s * STG;
        __half* Gs = As + ASTG;
        __half* Us = Gs + BSTG;
        #pragma unroll
        for (int i = tid; i < NCH; i += 256) {
            int r = i >> 2, c = (i & 3) << 3;
            if (r < BM) cp16(&As[r * SROW2 + c], &A[(size_t)(m0 + r) * K + k0 + c]);
            else if (r < BM + 128) {
                int rb = r - BM;
                cp16(&Gs[rb * SROW2 + c], &G[(size_t)(n0 + rb) * K + k0 + c]);
            } else {
                int rb = r - BM - 128;
                cp16(&Us[rb * SROW2 + c], &U[(size_t)(n0 + rb) * K + k0 + c]);
            }
        }
        CP_COMMIT();
    };

    uint32_t a_off[2], g_off[2], u_off[2];
    #pragma unroll
    for (int i = 0; i < 2; i++)
        a_off[i] = (uint32_t)(((wm * 32 + i * 16 + (g8 & 1) * 8 + r8) * SROW2) * 2
                              + (g8 >> 1) * 16);
    #pragma unroll
    for (int jj = 0; jj < 2; jj++) {
        uint32_t row = (uint32_t)(wn * 32 + jj * 16 + (g8 >> 1) * 8 + r8);
        g_off[jj] = (uint32_t)(ASTG * 2 + (row * SROW2) * 2 + (g8 & 1) * 16);
        u_off[jj] = g_off[jj] + BSTG * 2;
    }

    load_stage(0, 0);
    load_stage(1, 1);

    for (int kt = 0; kt < KT; kt++) {
        int s = kt % 3;
        if (kt + 1 < KT) CP_WAIT1(); else CP_WAIT0();
        __syncthreads();
        if (kt + 2 < KT) load_stage(kt + 2, (kt + 2) % 3);
        uint32_t base = smem_u32(tiles + s * STG);
        #pragma unroll
        for (int ks = 0; ks < 2; ks++) {
            uint32_t kofs = base + ks * 32;
            uint32_t af[2][4];
            #pragma unroll
            for (int i = 0; i < 2; i++)
                ldm_x4(af[i][0], af[i][1], af[i][2], af[i][3], kofs + a_off[i]);
            uint32_t gf[4][2], uf[4][2];
            #pragma unroll
            for (int jj = 0; jj < 2; jj++) {
                uint32_t m0r, m1r, m2r, m3r;
                ldm_x4(m0r, m1r, m2r, m3r, kofs + g_off[jj]);
                gf[2 * jj + 0][0] = m0r; gf[2 * jj + 0][1] = m1r;
                gf[2 * jj + 1][0] = m2r; gf[2 * jj + 1][1] = m3r;
                ldm_x4(m0r, m1r, m2r, m3r, kofs + u_off[jj]);
                uf[2 * jj + 0][0] = m0r; uf[2 * jj + 0][1] = m1r;
                uf[2 * jj + 1][0] = m2r; uf[2 * jj + 1][1] = m3r;
            }
            #pragma unroll
            for (int i = 0; i < 2; i++)
                #pragma unroll
                for (int j = 0; j < 4; j++) {
                    mma_f16(accg[i][j], af[i], gf[j][0], gf[j][1]);
                    mma_f16(accu[i][j], af[i], uf[j][0], uf[j][1]);
                }
        }
    }

    #pragma unroll
    for (int i = 0; i < 2; i++) {
        #pragma unroll
        for (int j = 0; j < 4; j++) {
            int rr = wm * 32 + i * 16 + gid;
            int m = m0 + rr;
            int n = n0 + wn * 32 + j * 8 + 2 * tig;
            #pragma unroll
            for (int hh = 0; hh < 2; hh++) {
                float rv = rs[rr + hh * 8];
                int mm = m + hh * 8;
                float gg0 = accg[i][j][hh * 2 + 0] * rv, gg1 = accg[i][j][hh * 2 + 1] * rv;
                float v0 = accu[i][j][hh * 2 + 0] * rv * gg0 / (1.0f + __expf(-gg0));
                float v1 = accu[i][j][hh * 2 + 1] * rv * gg1 / (1.0f + __expf(-gg1));
                size_t off = (size_t)mm * N + n;
                *(__half2*)&C[off] = __floats2half2_rn(v0, v1);
            }
        }
    }
}

// ---------------- fp16 flash attention (double-buffered K/V) ---------------------
#define SP 68

__global__ void __launch_bounds__(256) attn_mma_kernel(
    const __half* __restrict__ q, const __half* __restrict__ k,
    const __half* __restrict__ v, __half* __restrict__ o)
{
    extern __shared__ char smraw[];
    __half* Qs = (__half*)smraw;
    __half* Kb = Qs + 64 * SROWH;
    __half* Vb = Kb + 2 * 64 * SROWH;
    __half* Ps = Vb + 2 * 64 * SROWH;
    float*  Ss = (float*)(Ps + 64 * SROWH);
    float*  Al = Ss + 64 * SP;
    float*  Ll = Al + 64;

    int qt = blockIdx.x, h = blockIdx.y;
    int s0 = qt * 64;
    int key0 = (s0 < S0) ? 0 : S0;
    int nkt  = (s0 < S0) ? 16 : 8;

    int tid = threadIdx.x;
    int warp = tid >> 5, lane = tid & 31;
    int gid = lane >> 2, tig = lane & 3;
    int g8 = lane >> 3, r8 = lane & 7;
    int wm = warp >> 1, wn = warp & 1;
    int qq = tid >> 2, kg = tid & 3;

    auto load_tile = [&](int kt) {
        __half* Kd = Kb + (kt & 1) * 64 * SROWH;
        __half* Vd = Vb + (kt & 1) * 64 * SROWH;
        for (int i = tid; i < 1024; i += 256) {
            int sel = i >> 9;
            int i2 = i & 511;
            int r = i2 >> 3, c = (i2 & 7) << 3;
            size_t g = (size_t)(key0 + kt * 64 + r) * HID + h * HD + c;
            if (sel == 0) cp16(&Kd[r * SROWH + c], &k[g]);
            else          cp16(&Vd[r * SROWH + c], &v[g]);
        }
        CP_COMMIT();
    };

    for (int i = tid; i < 512; i += 256) {
        int r = i >> 3, c = (i & 7) << 3;
        cp16(&Qs[r * SROWH + c], &q[(size_t)(s0 + r) * HID + h * HD + c]);
    }
    CP_COMMIT();
    load_tile(0);

    float m_prev = -1e30f, lsum = 0.f;
    float oacc[4][4];
    #pragma unroll
    for (int j = 0; j < 4; j++)
        #pragma unroll
        for (int l = 0; l < 4; l++) oacc[j][l] = 0.f;

    int arow0 = wm * 16 + gid;

    uint32_t qa_off = (uint32_t)(((wm * 16 + (g8 & 1) * 8 + r8) * SROWH) * 2 + (g8 >> 1) * 16);
    uint32_t kb_off[2];
    #pragma unroll
    for (int jj = 0; jj < 2; jj++)
        kb_off[jj] = (uint32_t)(((wn * 32 + jj * 16 + (g8 >> 1) * 8 + r8) * SROWH) * 2
                                + (g8 & 1) * 16);

    uint32_t qbase = smem_u32(Qs);
    uint32_t pbase = smem_u32(Ps);

    for (int kt = 0; kt < nkt; kt++) {
        CP_WAIT0();
        __syncthreads();
        if (kt + 1 < nkt) load_tile(kt + 1);

        uint32_t kbase = smem_u32(Kb + (kt & 1) * 64 * SROWH);
        uint32_t vbase = smem_u32(Vb + (kt & 1) * 64 * SROWH);

        float sc[4][4];
        #pragma unroll
        for (int j = 0; j < 4; j++)
            #pragma unroll
            for (int l = 0; l < 4; l++) sc[j][l] = 0.f;
        #pragma unroll
        for (int ks = 0; ks < 4; ks++) {
            uint32_t kofs = ks * 32;
            uint32_t aq[4];
            ldm_x4(aq[0], aq[1], aq[2], aq[3], qbase + kofs + qa_off);
            uint32_t bf[4][2];
            #pragma unroll
            for (int jj = 0; jj < 2; jj++) {
                uint32_t m0r, m1r, m2r, m3r;
                ldm_x4(m0r, m1r, m2r, m3r, kbase + kofs + kb_off[jj]);
                bf[2 * jj + 0][0] = m0r; bf[2 * jj + 0][1] = m1r;
                bf[2 * jj + 1][0] = m2r; bf[2 * jj + 1][1] = m3r;
            }
            #pragma unroll
            for (int j = 0; j < 4; j++)
                mma_f16(sc[j], aq, bf[j][0], bf[j][1]);
        }
        #pragma unroll
        for (int j = 0; j < 4; j++) {
            int cn = wn * 32 + j * 8 + 2 * tig;
            Ss[arow0 * SP + cn]           = sc[j][0];
            Ss[arow0 * SP + cn + 1]       = sc[j][1];
            Ss[(arow0 + 8) * SP + cn]     = sc[j][2];
            Ss[(arow0 + 8) * SP + cn + 1] = sc[j][3];
        }
        __syncthreads();

        {
            float e[16];
            int base = qq * SP + kg * 16;
            float mloc = -1e30f;
            #pragma unroll
            for (int i = 0; i < 16; i++) { e[i] = Ss[base + i]; mloc = fmaxf(mloc, e[i]); }
            mloc = fmaxf(mloc, __shfl_xor_sync(0xffffffffu, mloc, 1));
            mloc = fmaxf(mloc, __shfl_xor_sync(0xffffffffu, mloc, 2));
            float m_new = fmaxf(m_prev, mloc);
            float alpha = __expf(m_prev - m_new);
            float lrow = 0.f;
            int pb = qq * SROWH + kg * 16;
            #pragma unroll
            for (int i = 0; i < 16; i += 2) {
                float e0 = __expf(e[i]     - m_new);
                float e1 = __expf(e[i + 1] - m_new);
                lrow += e0 + e1;
                *(__half2*)&Ps[pb + i] = __floats2half2_rn(e0, e1);
            }
            lrow += __shfl_xor_sync(0xffffffffu, lrow, 1);
            lrow += __shfl_xor_sync(0xffffffffu, lrow, 2);
            lsum = lsum * alpha + lrow;
            m_prev = m_new;
            if (kg == 0) Al[qq] = alpha;
        }
        __syncthreads();

        float a_r0 = Al[arow0], a_r1 = Al[arow0 + 8];
        #pragma unroll
        for (int j = 0; j < 4; j++) {
            oacc[j][0] *= a_r0; oacc[j][1] *= a_r0;
            oacc[j][2] *= a_r1; oacc[j][3] *= a_r1;
        }

        #pragma unroll
        for (int ks = 0; ks < 4; ks++) {
            uint32_t ap[4];
            ldm_x4(ap[0], ap[1], ap[2], ap[3], pbase + ks * 32 + qa_off);
            uint32_t vf[4][2];
            #pragma unroll
            for (int jj = 0; jj < 2; jj++) {
                uint32_t addr = vbase
                    + (uint32_t)(((ks * 16 + (g8 & 1) * 8 + r8) * SROWH) * 2
                                 + (wn * 32 + jj * 16) * 2 + (g8 >> 1) * 16);
                uint32_t m0r, m1r, m2r, m3r;
                ldm_x4t(m0r, m1r, m2r, m3r, addr);
                vf[2 * jj + 0][0] = m0r; vf[2 * jj + 0][1] = m1r;
                vf[2 * jj + 1][0] = m2r; vf[2 * jj + 1][1] = m3r;
            }
            #pragma unroll
            for (int j = 0; j < 4; j++)
                mma_f16(oacc[j], ap, vf[j][0], vf[j][1]);
        }
        __syncthreads();
    }

    if (kg == 0) Ll[qq] = lsum;
    __syncthreads();
    float inv0 = 1.0f / Ll[arow0];
    float inv1 = 1.0f / Ll[arow0 + 8];
    #pragma unroll
    for (int j = 0; j < 4; j++) {
        int cn = wn * 32 + j * 8 + 2 * tig;
        size_t o0 = (size_t)(s0 + arow0) * HID + h * HD + cn;
        size_t o1 = (size_t)(s0 + arow0 + 8) * HID + h * HD + cn;
        *(__half2*)&o[o0] = __floats2half2_rn(oacc[j][0] * inv0, oacc[j][1] * inv0);
        *(__half2*)&o[o1] = __floats2half2_rn(oacc[j][2] * inv1, oacc[j][3] * inv1);
    }
}

// ---------------- host orchestration ---------------------------------------------
extern "C" void kernel_launch(void* const* d_in, const int* in_sizes, int n_in,
                              void* d_out, int out_size) {
    const float* img0        = (const float*)d_in[0];
    const float* img1        = (const float*)d_in[1];
    const float* conv_w      = (const float*)d_in[2];
    const float* ln_pre_w    = (const float*)d_in[3];
    const float* attn_norm_w = (const float*)d_in[4];
    const float* q_w         = (const float*)d_in[5];
    const float* k_w         = (const float*)d_in[6];
    const float* v_w         = (const float*)d_in[7];
    const float* o_w         = (const float*)d_in[8];
    const float* ffn_norm_w  = (const float*)d_in[9];
    const float* gate_w      = (const float*)d_in[10];
    const float* up_w        = (const float*)d_in[11];
    const float* down_w      = (const float*)d_in[12];
    float* out = (float*)d_out;

    float *p_x, *p_h2, *p_pa, *p_pf;
    __half *p_xpatch, *p_ax, *p_ax2, *p_q, *p_k, *p_v, *p_ao, *p_t;
    __half *p_wconv, *p_wq, *p_wk, *p_wv, *p_wo, *p_wg, *p_wu, *p_wd;
    cudaGetSymbolAddress((void**)&p_x,  g_x);
    cudaGetSymbolAddress((void**)&p_h2, g_h2);
    cudaGetSymbolAddress((void**)&p_pa, g_pa);
    cudaGetSymbolAddress((void**)&p_pf, g_pf);
    cudaGetSymbolAddress((void**)&p_xpatch, a_xpatch);
    cudaGetSymbolAddress((void**)&p_ax,  a_x);
    cudaGetSymbolAddress((void**)&p_ax2, a_x2);
    cudaGetSymbolAddress((void**)&p_q,  a_q);
    cudaGetSymbolAddress((void**)&p_k,  a_k);
    cudaGetSymbolAddress((void**)&p_v,  a_v);
    cudaGetSymbolAddress((void**)&p_ao, a_ao);
    cudaGetSymbolAddress((void**)&p_t,  a_t);
    cudaGetSymbolAddress((void**)&p_wconv, h_wconv);
    cudaGetSymbolAddress((void**)&p_wq, h_wq);
    cudaGetSymbolAddress((void**)&p_wk, h_wk);
    cudaGetSymbolAddress((void**)&p_wv, h_wv);
    cudaGetSymbolAddress((void**)&p_wo, h_wo);
    cudaGetSymbolAddress((void**)&p_wg, h_wg);
    cudaGetSymbolAddress((void**)&p_wu, h_wu);
    cudaGetSymbolAddress((void**)&p_wd, h_wd);

    const int SMEM64  = 3 * (64 + 128) * SROWH * 2;   // 82944
    const int SMEMGU  = 3 * (64 + 256) * SROW2 * 2;   // 76800
    const int ASMEM   = 6 * 64 * SROWH * 2 + 64 * SP * 4 + 2 * 64 * 4;
    cudaFuncSetAttribute((const void*)gemm_f16<0, false, 0>, cudaFuncAttributeMaxDynamicSharedMemorySize, SMEM64);
    cudaFuncSetAttribute((const void*)gemm_f16<1, false, 0>, cudaFuncAttributeMaxDynamicSharedMemorySize, SMEM64);
    cudaFuncSetAttribute((const void*)gemm_f16<1, false, 1>, cudaFuncAttributeMaxDynamicSharedMemorySize, SMEM64);
    cudaFuncSetAttribute((const void*)gemm_qkv,              cudaFuncAttributeMaxDynamicSharedMemorySize, SMEM64);
    cudaFuncSetAttribute((const void*)gemm_gateup,           cudaFuncAttributeMaxDynamicSharedMemorySize, SMEMGU);
    cudaFuncSetAttribute((const void*)attn_mma_kernel,       cudaFuncAttributeMaxDynamicSharedMemorySize, ASMEM);

    // ---- side stream: weight conversion (norm weights folded) ----
    cudaStream_t s2;
    cudaStreamCreateWithFlags(&s2, cudaStreamNonBlocking);
    cudaEvent_t evFork, evConv, evL[NLAYERS];
    cudaEventCreateWithFlags(&evFork, cudaEventDisableTiming);
    cudaEventCreateWithFlags(&evConv, cudaEventDisableTiming);
    for (int l = 0; l < NLAYERS; l++) cudaEventCreateWithFlags(&evL[l], cudaEventDisableTiming);

    cudaEventRecord(evFork, 0);
    cudaStreamWaitEvent(s2, evFork, 0);

    auto cvt = [&](const float* src, __half* dst, int n) {
        f2h_kernel<<<(n / 16 + 255) / 256, 256, 0, s2>>>(src, dst, n / 16);
    };
    auto cvtn = [&](const float* src, const float* nw, __half* dst, int n) {
        f2h_norm_kernel<<<(n / 16 + 255) / 256, 256, 0, s2>>>(src, nw, dst, n / 16);
    };
    cvt(conv_w, p_wconv, HID * KPATCH);
    cudaEventRecord(evConv, s2);
    for (int l = 0; l < NLAYERS; l++) {
        const float* anw = attn_norm_w + l * HID;
        const float* fnw = ffn_norm_w  + l * HID;
        cvtn(q_w    + (size_t)l * HID * HID,   anw, p_wq + (size_t)l * HID * HID,   HID * HID);
        cvtn(k_w    + (size_t)l * HID * HID,   anw, p_wk + (size_t)l * HID * HID,   HID * HID);
        cvtn(v_w    + (size_t)l * HID * HID,   anw, p_wv + (size_t)l * HID * HID,   HID * HID);
        cvt (o_w    + (size_t)l * HID * HID,        p_wo + (size_t)l * HID * HID,   HID * HID);
        cvtn(gate_w + (size_t)l * INTER * HID, fnw, p_wg + (size_t)l * INTER * HID, INTER * HID);
        cvtn(up_w   + (size_t)l * INTER * HID, fnw, p_wu + (size_t)l * INTER * HID, INTER * HID);
        cvt (down_w + (size_t)l * HID * INTER,      p_wd + (size_t)l * HID * INTER, HID * INTER);
        cudaEventRecord(evL[l], s2);
    }

    dim3 grid_n1k(HID / 128, S_TOK / 64);       // (8, 24)
    dim3 grid_qkv(HID / 128, S_TOK / 64, 3);    // (8, 24, 3)
    dim3 grid_gu (INTER / 128, S_TOK / 64);     // (32, 24)

    // merged im2col + rope table
    prep_kernel<<<IM2COL_BLOCKS + S_TOK / 4, 256>>>(img0, img1);
    cudaStreamWaitEvent(0, evConv, 0);
    gemm_f16<0, false, 0><<<grid_n1k, 256, SMEM64>>>(
        p_xpatch, p_wconv, nullptr, p_h2, nullptr, nullptr, HID, KPATCH);

    // ln_pre: x fp32 + half copy + attn-rms sumsq partials
    lnpre_kernel<<<S_TOK, 256>>>(p_h2, ln_pre_w, p_x, p_ax, p_pa);

    for (int l = 0; l < NLAYERS; l++) {
        const __half* qw = p_wq + (size_t)l * HID * HID;
        const __half* kw = p_wk + (size_t)l * HID * HID;
        const __half* vw = p_wv + (size_t)l * HID * HID;
        const __half* ow = p_wo + (size_t)l * HID * HID;
        const __half* gw = p_wg + (size_t)l * INTER * HID;
        const __half* uw = p_wu + (size_t)l * INTER * HID;
        const __half* dw = p_wd + (size_t)l * HID * INTER;

        cudaStreamWaitEvent(0, evL[l], 0);   // layer-l weights ready

        gemm_qkv<<<grid_qkv, 256, SMEM64>>>(p_ax, qw, kw, vw, p_q, p_k, p_v, p_pa, HID);

        attn_mma_kernel<<<dim3(S_TOK / 64, HEADS), 256, ASMEM>>>(p_q, p_k, p_v, p_ao);

        gemm_f16<1, false, 1><<<grid_n1k, 256, SMEM64>>>(
            p_ao, ow, p_x, p_h2, p_ax2, p_pf, HID, HID);

        gemm_gateup<<<grid_gu, 256, SMEMGU>>>(p_ax2, gw, uw, p_t, p_pf, INTER, HID);

        if (l < NLAYERS - 1) {
            gemm_f16<1, false, 1><<<grid_n1k, 256, SMEM64>>>(
                p_t, dw, p_h2, p_x, p_ax, p_pa, HID, INTER);
        } else {
            gemm_f16<1, false, 0><<<grid_n1k, 256, SMEM64>>>(
                p_t, dw, p_h2, out, nullptr, nullptr, HID, INTER);
        }
    }
    // streams/events intentionally not destroyed (active graph capture).
}